// round 6
// baseline (speedup 1.0000x reference)
#include <cuda_runtime.h>
#include <cuda_fp16.h>
#include <math.h>
#include <cstdint>

#define BB 2
#define TT 2048
#define DD 1024
#define NH 16
#define HD 64
#define LOG2E_ 1.442695041f

// ---------------------------------------------------------------------------
// Scratch (__device__ globals, allocation-free rule)
// ---------------------------------------------------------------------------
__device__ __half g_xhi[4194304], g_xlo[4194304];        // X split       [4096][1024]
__device__ __half g_wthi[3145728], g_wtlo[3145728];      // wq/wk/wv^T    [3][1024 n][1024 k]
__device__ __half g_wohi[1048576], g_wolo[1048576];      // wo split      [1024 d][1024 k]
__device__ __half g_qhi[4194304], g_qlo[4194304];        // q (scaled)    [4096][1024]
__device__ __half g_khi[4194304], g_klo[4194304];        // k             [4096][1024]
__device__ __half g_v16[4194304];                        // v fp16        [4096][1024]
__device__ __half g_ahi[4194304], g_alo[4194304];        // attn out      [4096][1024]

// ---------------------------------------------------------------------------
// PTX helpers
// ---------------------------------------------------------------------------
__device__ __forceinline__ uint32_t smem_u32(const void* p) {
    uint32_t a;
    asm("{ .reg .u64 t; cvta.to.shared.u64 t, %1; cvt.u32.u64 %0, t; }" : "=r"(a) : "l"(p));
    return a;
}
__device__ __forceinline__ void ldsm_x4(uint32_t* r, uint32_t a) {
    asm volatile("ldmatrix.sync.aligned.m8n8.x4.shared.b16 {%0,%1,%2,%3}, [%4];"
                 : "=r"(r[0]), "=r"(r[1]), "=r"(r[2]), "=r"(r[3]) : "r"(a));
}
__device__ __forceinline__ void ldsm_x4_t(uint32_t* r, uint32_t a) {
    asm volatile("ldmatrix.sync.aligned.m8n8.x4.trans.shared.b16 {%0,%1,%2,%3}, [%4];"
                 : "=r"(r[0]), "=r"(r[1]), "=r"(r[2]), "=r"(r[3]) : "r"(a));
}
__device__ __forceinline__ void mma16816(float* c, const uint32_t* a, uint32_t b0, uint32_t b1) {
    asm volatile(
        "mma.sync.aligned.m16n8k16.row.col.f32.f16.f16.f32 "
        "{%0,%1,%2,%3}, {%4,%5,%6,%7}, {%8,%9}, {%0,%1,%2,%3};"
        : "+f"(c[0]), "+f"(c[1]), "+f"(c[2]), "+f"(c[3])
        : "r"(a[0]), "r"(a[1]), "r"(a[2]), "r"(a[3]), "r"(b0), "r"(b1));
}
#define CP_A16(dst, src) \
    asm volatile("cp.async.cg.shared.global [%0], [%1], 16;" :: "r"(dst), "l"(src))
#define CP_COMMIT() asm volatile("cp.async.commit_group;" ::: "memory")
#define CP_WAIT0()  asm volatile("cp.async.wait_group 0;" ::: "memory")
#define CP_WAIT1()  asm volatile("cp.async.wait_group 1;" ::: "memory")

__device__ __forceinline__ float ex2(float x) {
    float y;
    asm("ex2.approx.ftz.f32 %0, %1;" : "=f"(y) : "f"(x));
    return y;
}

// swizzled byte offset, 64-half (128B) rows
__device__ __forceinline__ uint32_t swz_h(int r, int k) {
    return (uint32_t)(r * 128 + (((k >> 3) ^ (r & 7)) << 4) + ((k & 7) << 1));
}
__device__ __forceinline__ uint32_t pack_h2(__half a, __half b) {
    __half2 h = __halves2half2(a, b);
    return *(uint32_t*)&h;
}
__device__ __forceinline__ void split2(float x, float y, uint32_t& hi, uint32_t& lo) {
    __half hx = __float2half_rn(x), hy = __float2half_rn(y);
    hi = pack_h2(hx, hy);
    lo = pack_h2(__float2half_rn(x - __half2float(hx)),
                 __float2half_rn(y - __half2float(hy)));
}

// ---------------------------------------------------------------------------
// Split kernels (fp32 -> fp16 hi/lo)
// ---------------------------------------------------------------------------
__global__ __launch_bounds__(256) void split_kernel(
    const float* __restrict__ src, __half* __restrict__ hi, __half* __restrict__ lo, int n4)
{
    int i = blockIdx.x * 256 + threadIdx.x;
    if (i >= n4) return;
    float4 v = *(const float4*)&src[i * 4];
    uint32_t h0, l0, h1, l1;
    split2(v.x, v.y, h0, l0);
    split2(v.z, v.w, h1, l1);
    *(uint32_t*)&hi[i * 4] = h0; *(uint32_t*)&hi[i * 4 + 2] = h1;
    *(uint32_t*)&lo[i * 4] = l0; *(uint32_t*)&lo[i * 4 + 2] = l1;
}

__global__ __launch_bounds__(256) void transpose_split_kernel(
    const float* __restrict__ wq, const float* __restrict__ wk, const float* __restrict__ wv)
{
    __shared__ float t[32][33];
    const int z = blockIdx.z;
    const float* src = (z == 0) ? wq : (z == 1) ? wk : wv;
    __half* dhi = g_wthi + (size_t)z * 1048576;
    __half* dlo = g_wtlo + (size_t)z * 1048576;
    const int tx = threadIdx.x, ty = threadIdx.y;
    const int x0 = blockIdx.x * 32;  // k
    const int y0 = blockIdx.y * 32;  // n
#pragma unroll
    for (int i = 0; i < 4; ++i)
        t[ty + i * 8][tx] = src[(size_t)(x0 + ty + i * 8) * 1024 + y0 + tx];
    __syncthreads();
#pragma unroll
    for (int i = 0; i < 4; ++i) {
        float v = t[tx][ty + i * 8];
        __half h = __float2half_rn(v);
        dhi[(size_t)(y0 + ty + i * 8) * 1024 + x0 + tx] = h;
        dlo[(size_t)(y0 + ty + i * 8) * 1024 + x0 + tx] =
            __float2half_rn(v - __half2float(h));
    }
}

// ---------------------------------------------------------------------------
// Split-fp16 HMMA GEMM: C(4096x1024) = A @ B^T + bias. 3-term hi/lo split.
// Combined tiles: per 32-k chunk, A-tile [128 rows][64 halves] with cols 0..31
// = Ahi, 32..63 = Alo (same for B). All 3 terms issued from one smem stage.
// modes: 0=Q (scale+bias, split out), 1=K (bias, split out),
//        2=V (bias, fp16 out), 3=O (bias, fp32 out)
// ---------------------------------------------------------------------------
#define GC_STAGE 32768   // A 16KB + B 16KB
__global__ __launch_bounds__(256, 2) void gemm_split_kernel(
    const float* __restrict__ bq, const float* __restrict__ bk,
    const float* __restrict__ bv, const float* __restrict__ bo,
    const float* __restrict__ pds, float* __restrict__ out, int mode_base)
{
    extern __shared__ char smem[];
    const int mode = mode_base + blockIdx.z;

    const __half* Ahi = (mode < 3) ? g_xhi : g_ahi;
    const __half* Alo = (mode < 3) ? g_xlo : g_alo;
    const __half* Bhi = (mode < 3) ? g_wthi + (size_t)mode * 1048576 : g_wohi;
    const __half* Blo = (mode < 3) ? g_wtlo + (size_t)mode * 1048576 : g_wolo;
    const float* bias = (mode == 0) ? bq : (mode == 1) ? bk : (mode == 2) ? bv : bo;

    const int tid = threadIdx.x;
    const int wid = tid >> 5, lane = tid & 31;
    const int m0 = (wid & 3) * 32, n0 = (wid >> 2) * 64;
    const int row0 = blockIdx.y * 128, col0 = blockIdx.x * 128;
    const uint32_t sb = smem_u32(smem);
    const int lrow = lane & 15;
    const int lkof = (lane & 16) >> 1;

    // hoisted per-thread copy addresses: 4 units A + 4 units B
    const __half* gA[4];
    const __half* gB[4];
    uint32_t sOff[4];
#pragma unroll
    for (int it = 0; it < 4; ++it) {
        int idx = it * 256 + tid;             // 0..1023 (16B units of a 16KB tile)
        int r = idx >> 3, c8 = (idx & 7) << 3;
        sOff[it] = swz_h(r, c8);
        int inlo = (c8 >= 32);
        int kc = c8 & 31;
        gA[it] = (inlo ? Alo : Ahi) + (size_t)(row0 + r) * 1024 + kc;
        gB[it] = (inlo ? Blo : Bhi) + (size_t)(col0 + r) * 1024 + kc;
    }

    float acc[2][8][4];
#pragma unroll
    for (int i = 0; i < 2; ++i)
#pragma unroll
        for (int j = 0; j < 8; ++j)
#pragma unroll
            for (int c = 0; c < 4; ++c) acc[i][j][c] = 0.f;

    auto issue = [&](int k0, int st) {
        uint32_t a_dst = sb + st * GC_STAGE;
        uint32_t b_dst = a_dst + 16384;
#pragma unroll
        for (int it = 0; it < 4; ++it) {
            CP_A16(a_dst + sOff[it], gA[it] + k0);
            CP_A16(b_dst + sOff[it], gB[it] + k0);
        }
        CP_COMMIT();
    };

    issue(0, 0);
    for (int c = 0; c < 32; ++c) {
        if (c + 1 < 32) { issue((c + 1) * 32, (c + 1) & 1); CP_WAIT1(); }
        else            { CP_WAIT0(); }
        __syncthreads();
        const uint32_t aoff = sb + (c & 1) * GC_STAGE;
        const uint32_t boff = aoff + 16384;
#pragma unroll
        for (int ks = 0; ks < 32; ks += 16) {
            uint32_t af1[2][4], af2[2][4], bf[4][4];
#pragma unroll
            for (int mi = 0; mi < 2; ++mi) {
                ldsm_x4(af1[mi], aoff + swz_h(m0 + mi * 16 + lrow, ks + lkof));       // Ah
                ldsm_x4(af2[mi], aoff + swz_h(m0 + mi * 16 + lrow, ks + 32 + lkof));  // Al
            }
#pragma unroll
            for (int g = 0; g < 4; ++g)
                ldsm_x4(bf[g], boff + swz_h(n0 + g * 16 + lrow, ks + lkof));          // Bh
#pragma unroll
            for (int mi = 0; mi < 2; ++mi)
#pragma unroll
                for (int g = 0; g < 4; ++g) {
                    mma16816(acc[mi][2 * g],     af1[mi], bf[g][0], bf[g][2]);
                    mma16816(acc[mi][2 * g + 1], af1[mi], bf[g][1], bf[g][3]);
                    mma16816(acc[mi][2 * g],     af2[mi], bf[g][0], bf[g][2]);
                    mma16816(acc[mi][2 * g + 1], af2[mi], bf[g][1], bf[g][3]);
                }
#pragma unroll
            for (int g = 0; g < 4; ++g)
                ldsm_x4(bf[g], boff + swz_h(n0 + g * 16 + lrow, ks + 32 + lkof));     // Bl
#pragma unroll
            for (int mi = 0; mi < 2; ++mi)
#pragma unroll
                for (int g = 0; g < 4; ++g) {
                    mma16816(acc[mi][2 * g],     af1[mi], bf[g][0], bf[g][2]);
                    mma16816(acc[mi][2 * g + 1], af1[mi], bf[g][1], bf[g][3]);
                }
        }
        __syncthreads();
    }

    // epilogue
    const int frow = m0 + (lane >> 2);
    const int fcol = n0 + 2 * (lane & 3);
#pragma unroll
    for (int mi = 0; mi < 2; ++mi) {
#pragma unroll
        for (int nj = 0; nj < 8; ++nj) {
            int col = col0 + fcol + nj * 8;
            int r0 = row0 + frow + mi * 16;
            float b0 = bias[col], b1 = bias[col + 1];
            float v0 = acc[mi][nj][0] + b0, v1 = acc[mi][nj][1] + b1;
            float v2 = acc[mi][nj][2] + b0, v3 = acc[mi][nj][3] + b1;
            if (mode == 0) {
                // extra LOG2E folded in so softmax can use raw ex2
                float p0 = pds[col & 63], p1 = pds[(col + 1) & 63];
                float s0 = (LOG2E_ * LOG2E_ * 0.125f) * ((p0 > 20.f) ? p0 : log1pf(__expf(p0)));
                float s1 = (LOG2E_ * LOG2E_ * 0.125f) * ((p1 > 20.f) ? p1 : log1pf(__expf(p1)));
                v0 *= s0; v1 *= s1; v2 *= s0; v3 *= s1;
            }
            if (mode <= 1) {
                __half* Chi = (mode == 0) ? g_qhi : g_khi;
                __half* Clo = (mode == 0) ? g_qlo : g_klo;
                uint32_t h, l;
                split2(v0, v1, h, l);
                *(uint32_t*)&Chi[(size_t)r0 * 1024 + col] = h;
                *(uint32_t*)&Clo[(size_t)r0 * 1024 + col] = l;
                split2(v2, v3, h, l);
                *(uint32_t*)&Chi[(size_t)(r0 + 8) * 1024 + col] = h;
                *(uint32_t*)&Clo[(size_t)(r0 + 8) * 1024 + col] = l;
            } else if (mode == 2) {
                *(uint32_t*)&g_v16[(size_t)r0 * 1024 + col] =
                    pack_h2(__float2half_rn(v0), __float2half_rn(v1));
                *(uint32_t*)&g_v16[(size_t)(r0 + 8) * 1024 + col] =
                    pack_h2(__float2half_rn(v2), __float2half_rn(v3));
            } else {
                *(float2*)&out[(size_t)r0 * 1024 + col] = make_float2(v0, v1);
                *(float2*)&out[(size_t)(r0 + 8) * 1024 + col] = make_float2(v2, v3);
            }
        }
    }
}

// ---------------------------------------------------------------------------
// Flash attention, HMMA. Block = (128 q rows, head n, batch b), 256 thr / 8 warps.
// Warp owns 16 q rows. QK^T 3-term split; PV with split P (regs) + fp16 V.
// Softmax in log2 domain (ex2), LOG2E prefolded into q scale.
// smem: Qh,Ql [128][64] (32KB) + 2 stages of (Kh,Kl,V [64][64]) (48KB).
// ---------------------------------------------------------------------------
#define A_QOFF 0
#define A_KVOFF 32768
#define A_KVSTAGE 24576
#define ATTN_SMEM (32768 + 2 * 24576)
__global__ __launch_bounds__(256) void attn_hmma_kernel(const int* __restrict__ mask)
{
    extern __shared__ char smem[];
    const int tid = threadIdx.x;
    const int wid = tid >> 5, lane = tid & 31;
    const int q0 = blockIdx.x * 128;
    const int n  = blockIdx.y;
    const int b  = blockIdx.z;
    const uint32_t sb = smem_u32(smem);
    const int lrow = lane & 15;
    const int lkof = (lane & 16) >> 1;

    const size_t gq0 = (size_t)(b * TT + q0) * 1024 + n * 64;

    // prologue: Q hi+lo (32KB) + KV tile 0 in one cp.async group
#pragma unroll
    for (int it = 0; it < 4; ++it) {
        int idx = it * 256 + tid;           // 0..1023
        int r = idx >> 3, k8 = (idx & 7) << 3;
        size_t g = gq0 + (size_t)r * 1024 + k8;
        uint32_t o = swz_h(r, k8);
        CP_A16(sb + A_QOFF + o,         g_qhi + g);
        CP_A16(sb + A_QOFF + 16384 + o, g_qlo + g);
    }
    auto issue_kv = [&](int st, int stage) {
        size_t gk0 = (size_t)(b * TT + st * 64) * 1024 + n * 64;
        uint32_t base = sb + A_KVOFF + stage * A_KVSTAGE;
#pragma unroll
        for (int it = 0; it < 2; ++it) {
            int idx = it * 256 + tid;       // 0..511
            int r = idx >> 3, k8 = (idx & 7) << 3;
            size_t g = gk0 + (size_t)r * 1024 + k8;
            uint32_t o = swz_h(r, k8);
            CP_A16(base + o,         g_khi + g);
            CP_A16(base + 8192 + o,  g_klo + g);
            CP_A16(base + 16384 + o, g_v16 + g);
        }
        CP_COMMIT();
    };
    issue_kv(0, 0);

    uint32_t qh[4][4], ql[4][4];
    float oacc[8][4];
#pragma unroll
    for (int j = 0; j < 8; ++j)
#pragma unroll
        for (int c = 0; c < 4; ++c) oacc[j][c] = 0.f;
    float m_0 = -3.0e38f, m_1 = -3.0e38f, l_0 = 0.f, l_1 = 0.f;

    const int qrl = q0 + wid * 16 + (lane >> 2);
    const int mcol0 = 2 * (lane & 3);

    for (int st = 0; st < TT / 64; ++st) {
        if (st + 1 < TT / 64) { issue_kv(st + 1, (st + 1) & 1); CP_WAIT1(); }
        else                  { CP_WAIT0(); }
        __syncthreads();

        if (st == 0) {
#pragma unroll
            for (int kt = 0; kt < 4; ++kt) {
                uint32_t o = swz_h(wid * 16 + lrow, kt * 16 + lkof);
                ldsm_x4(qh[kt], sb + A_QOFF + o);
                ldsm_x4(ql[kt], sb + A_QOFF + 16384 + o);
            }
        }

        const uint32_t kvb = sb + A_KVOFF + (st & 1) * A_KVSTAGE;

        // ---- S = QK^T (3 terms) ----
        float sacc[8][4];
#pragma unroll
        for (int j = 0; j < 8; ++j)
#pragma unroll
            for (int c = 0; c < 4; ++c) sacc[j][c] = 0.f;
#pragma unroll
        for (int kt = 0; kt < 12; ++kt) {
            const int t = kt >> 2, kq = kt & 3;
            const uint32_t* af = (t < 2) ? qh[kq] : ql[kq];
            const uint32_t kb = (t == 1) ? kvb + 8192 : kvb;
            uint32_t bf[4][4];
#pragma unroll
            for (int g = 0; g < 4; ++g)
                ldsm_x4(bf[g], kb + swz_h(g * 16 + lrow, kq * 16 + lkof));
#pragma unroll
            for (int g = 0; g < 4; ++g) {
                mma16816(sacc[2 * g],     af, bf[g][0], bf[g][2]);
                mma16816(sacc[2 * g + 1], af, bf[g][1], bf[g][3]);
            }
        }

        // ---- mask ----
#pragma unroll
        for (int j = 0; j < 8; ++j) {
            int col = st * 64 + j * 8 + mcol0;
            int2 mv0 = *(const int2*)&mask[(size_t)(b * TT + qrl) * TT + col];
            int2 mv1 = *(const int2*)&mask[(size_t)(b * TT + qrl + 8) * TT + col];
            if (!mv0.x) sacc[j][0] = -1.0e9f;
            if (!mv0.y) sacc[j][1] = -1.0e9f;
            if (!mv1.x) sacc[j][2] = -1.0e9f;
            if (!mv1.y) sacc[j][3] = -1.0e9f;
        }

        // ---- online softmax (log2 domain) ----
        float mx0 = -3.0e38f, mx1 = -3.0e38f;
#pragma unroll
        for (int j = 0; j < 8; ++j) {
            mx0 = fmaxf(mx0, fmaxf(sacc[j][0], sacc[j][1]));
            mx1 = fmaxf(mx1, fmaxf(sacc[j][2], sacc[j][3]));
        }
        mx0 = fmaxf(mx0, __shfl_xor_sync(0xffffffffu, mx0, 1));
        mx0 = fmaxf(mx0, __shfl_xor_sync(0xffffffffu, mx0, 2));
        mx1 = fmaxf(mx1, __shfl_xor_sync(0xffffffffu, mx1, 1));
        mx1 = fmaxf(mx1, __shfl_xor_sync(0xffffffffu, mx1, 2));
        float mn0 = fmaxf(m_0, mx0), mn1 = fmaxf(m_1, mx1);
        float f0 = ex2(m_0 - mn0), f1 = ex2(m_1 - mn1);
        m_0 = mn0; m_1 = mn1;
        float rs0 = 0.f, rs1 = 0.f;
#pragma unroll
        for (int j = 0; j < 8; ++j) {
            sacc[j][0] = ex2(sacc[j][0] - mn0);
            sacc[j][1] = ex2(sacc[j][1] - mn0);
            sacc[j][2] = ex2(sacc[j][2] - mn1);
            sacc[j][3] = ex2(sacc[j][3] - mn1);
            rs0 += sacc[j][0] + sacc[j][1];
            rs1 += sacc[j][2] + sacc[j][3];
        }
        rs0 += __shfl_xor_sync(0xffffffffu, rs0, 1);
        rs0 += __shfl_xor_sync(0xffffffffu, rs0, 2);
        rs1 += __shfl_xor_sync(0xffffffffu, rs1, 1);
        rs1 += __shfl_xor_sync(0xffffffffu, rs1, 2);
        l_0 = l_0 * f0 + rs0;
        l_1 = l_1 * f1 + rs1;
#pragma unroll
        for (int j = 0; j < 8; ++j) {
            oacc[j][0] *= f0; oacc[j][1] *= f0;
            oacc[j][2] *= f1; oacc[j][3] *= f1;
        }

        // ---- O += P V (P split, V fp16) ----
#pragma unroll
        for (int kt = 0; kt < 4; ++kt) {
            uint32_t ph[4], pl[4];
            {
                const float* sA = sacc[2 * kt];
                const float* sB = sacc[2 * kt + 1];
                split2(sA[0], sA[1], ph[0], pl[0]);
                split2(sA[2], sA[3], ph[1], pl[1]);
                split2(sB[0], sB[1], ph[2], pl[2]);
                split2(sB[2], sB[3], ph[3], pl[3]);
            }
            uint32_t vf[4][4];
#pragma unroll
            for (int g = 0; g < 4; ++g)
                ldsm_x4_t(vf[g], kvb + 16384 + swz_h(kt * 16 + lrow, g * 16 + lkof));
#pragma unroll
            for (int g = 0; g < 4; ++g) {
                mma16816(oacc[2 * g],     ph, vf[g][0], vf[g][1]);
                mma16816(oacc[2 * g],     pl, vf[g][0], vf[g][1]);
                mma16816(oacc[2 * g + 1], ph, vf[g][2], vf[g][3]);
                mma16816(oacc[2 * g + 1], pl, vf[g][2], vf[g][3]);
            }
        }
        __syncthreads();
    }

    // ---- epilogue: normalize + split fp16 store ----
    const float inv0 = 1.0f / l_0, inv1 = 1.0f / l_1;
    const size_t m_lo = (size_t)(b * TT + qrl) * 1024 + n * 64;
#pragma unroll
    for (int j = 0; j < 8; ++j) {
        int col = j * 8 + mcol0;
        uint32_t h, l;
        split2(oacc[j][0] * inv0, oacc[j][1] * inv0, h, l);
        *(uint32_t*)&g_ahi[m_lo + col] = h;
        *(uint32_t*)&g_alo[m_lo + col] = l;
        split2(oacc[j][2] * inv1, oacc[j][3] * inv1, h, l);
        *(uint32_t*)&g_ahi[m_lo + 8 * 1024 + col] = h;
        *(uint32_t*)&g_alo[m_lo + 8 * 1024 + col] = l;
    }
}

// ---------------------------------------------------------------------------
// Launch
// ---------------------------------------------------------------------------
extern "C" void kernel_launch(void* const* d_in, const int* in_sizes, int n_in,
                              void* d_out, int out_size)
{
    const float* x    = (const float*)d_in[0];
    const int*   mask = (const int*)  d_in[1];
    const float* wq   = (const float*)d_in[2];
    const float* bq   = (const float*)d_in[3];
    const float* wk   = (const float*)d_in[4];
    const float* bk   = (const float*)d_in[5];
    const float* wv   = (const float*)d_in[6];
    const float* bv   = (const float*)d_in[7];
    const float* wo   = (const float*)d_in[8];
    const float* bo   = (const float*)d_in[9];
    const float* pds  = (const float*)d_in[10];
    float* out = (float*)d_out;

    const int gemm_smem = 2 * GC_STAGE;  // 64KB
    cudaFuncSetAttribute(gemm_split_kernel, cudaFuncAttributeMaxDynamicSharedMemorySize, gemm_smem);
    cudaFuncSetAttribute(attn_hmma_kernel, cudaFuncAttributeMaxDynamicSharedMemorySize, ATTN_SMEM);

    __half *xhi, *xlo, *wohi, *wolo;
    cudaGetSymbolAddress((void**)&xhi, g_xhi);
    cudaGetSymbolAddress((void**)&xlo, g_xlo);
    cudaGetSymbolAddress((void**)&wohi, g_wohi);
    cudaGetSymbolAddress((void**)&wolo, g_wolo);

    split_kernel<<<4096, 256>>>(x, xhi, xlo, 1048576);
    split_kernel<<<1024, 256>>>(wo, wohi, wolo, 262144);
    transpose_split_kernel<<<dim3(32, 32, 3), dim3(32, 8)>>>(wq, wk, wv);

    gemm_split_kernel<<<dim3(8, 32, 3), 256, gemm_smem>>>(bq, bk, bv, bo, pds, out, 0);
    attn_hmma_kernel<<<dim3(16, 16, 2), 256, ATTN_SMEM>>>(mask);
    gemm_split_kernel<<<dim3(8, 32, 1), 256, gemm_smem>>>(bq, bk, bv, bo, pds, out, 3);
}

// round 8
// speedup vs baseline: 1.1222x; 1.1222x over previous
#include <cuda_runtime.h>
#include <cuda_fp16.h>
#include <math.h>
#include <cstdint>

#define BB 2
#define TT 2048
#define DD 1024
#define NH 16
#define HD 64
#define LOG2E_ 1.442695041f

// ---------------------------------------------------------------------------
// Scratch (__device__ globals, allocation-free rule)
// ---------------------------------------------------------------------------
__device__ __half g_xhi[4194304], g_xlo[4194304];        // X split       [4096][1024]
__device__ __half g_wthi[3145728], g_wtlo[3145728];      // wq/wk/wv^T    [3][1024 n][1024 k]
__device__ __half g_wohi[1048576], g_wolo[1048576];      // wo split      [1024 d][1024 k]
__device__ __half g_qhi[4194304], g_qlo[4194304];        // q (scaled)    [4096][1024]
__device__ __half g_khi[4194304], g_klo[4194304];        // k             [4096][1024]
__device__ __half g_v16[4194304];                        // v fp16        [4096][1024]
__device__ __half g_ahi[4194304], g_alo[4194304];        // attn out      [4096][1024]
__device__ unsigned char g_mask8[8388608];               // mask bytes    [2][2048][2048]

// ---------------------------------------------------------------------------
// PTX helpers
// ---------------------------------------------------------------------------
__device__ __forceinline__ uint32_t smem_u32(const void* p) {
    uint32_t a;
    asm("{ .reg .u64 t; cvta.to.shared.u64 t, %1; cvt.u32.u64 %0, t; }" : "=r"(a) : "l"(p));
    return a;
}
__device__ __forceinline__ void ldsm_x4(uint32_t* r, uint32_t a) {
    asm volatile("ldmatrix.sync.aligned.m8n8.x4.shared.b16 {%0,%1,%2,%3}, [%4];"
                 : "=r"(r[0]), "=r"(r[1]), "=r"(r[2]), "=r"(r[3]) : "r"(a));
}
__device__ __forceinline__ void ldsm_x4_t(uint32_t* r, uint32_t a) {
    asm volatile("ldmatrix.sync.aligned.m8n8.x4.trans.shared.b16 {%0,%1,%2,%3}, [%4];"
                 : "=r"(r[0]), "=r"(r[1]), "=r"(r[2]), "=r"(r[3]) : "r"(a));
}
__device__ __forceinline__ void mma16816(float* c, const uint32_t* a, uint32_t b0, uint32_t b1) {
    asm volatile(
        "mma.sync.aligned.m16n8k16.row.col.f32.f16.f16.f32 "
        "{%0,%1,%2,%3}, {%4,%5,%6,%7}, {%8,%9}, {%0,%1,%2,%3};"
        : "+f"(c[0]), "+f"(c[1]), "+f"(c[2]), "+f"(c[3])
        : "r"(a[0]), "r"(a[1]), "r"(a[2]), "r"(a[3]), "r"(b0), "r"(b1));
}
#define CP_A16(dst, src) \
    asm volatile("cp.async.cg.shared.global [%0], [%1], 16;" :: "r"(dst), "l"(src))
#define CP_COMMIT() asm volatile("cp.async.commit_group;" ::: "memory")
#define CP_WAIT0()  asm volatile("cp.async.wait_group 0;" ::: "memory")
#define CP_WAIT1()  asm volatile("cp.async.wait_group 1;" ::: "memory")

__device__ __forceinline__ float ex2(float x) {
    float y;
    asm("ex2.approx.ftz.f32 %0, %1;" : "=f"(y) : "f"(x));
    return y;
}

// swizzled byte offset, 64-half (128B) rows
__device__ __forceinline__ uint32_t swz_h(int r, int k) {
    return (uint32_t)(r * 128 + (((k >> 3) ^ (r & 7)) << 4) + ((k & 7) << 1));
}
__device__ __forceinline__ uint32_t pack_h2(__half a, __half b) {
    __half2 h = __halves2half2(a, b);
    return *(uint32_t*)&h;
}
__device__ __forceinline__ void split2(float x, float y, uint32_t& hi, uint32_t& lo) {
    __half hx = __float2half_rn(x), hy = __float2half_rn(y);
    hi = pack_h2(hx, hy);
    lo = pack_h2(__float2half_rn(x - __half2float(hx)),
                 __float2half_rn(y - __half2float(hy)));
}

// ---------------------------------------------------------------------------
// Preprocess kernels
// ---------------------------------------------------------------------------
__global__ __launch_bounds__(256) void split_kernel(
    const float* __restrict__ src, __half* __restrict__ hi, __half* __restrict__ lo, int n4)
{
    int i = blockIdx.x * 256 + threadIdx.x;
    if (i >= n4) return;
    float4 v = *(const float4*)&src[i * 4];
    uint32_t h0, l0, h1, l1;
    split2(v.x, v.y, h0, l0);
    split2(v.z, v.w, h1, l1);
    *(uint32_t*)&hi[i * 4] = h0; *(uint32_t*)&hi[i * 4 + 2] = h1;
    *(uint32_t*)&lo[i * 4] = l0; *(uint32_t*)&lo[i * 4 + 2] = l1;
}

// 2*2048*2048 = 8388608 ints total -> 2097152 int4 -> 8192 blocks of 256
__global__ __launch_bounds__(256) void mask_pack_kernel(const int* __restrict__ m)
{
    int i = blockIdx.x * 256 + threadIdx.x;   // one int4 per thread
    int4 v = *(const int4*)&m[i * 4];
    uchar4 o;
    o.x = (unsigned char)v.x; o.y = (unsigned char)v.y;
    o.z = (unsigned char)v.z; o.w = (unsigned char)v.w;
    *(uchar4*)&g_mask8[i * 4] = o;
}

__global__ __launch_bounds__(256) void transpose_split_kernel(
    const float* __restrict__ wq, const float* __restrict__ wk, const float* __restrict__ wv)
{
    __shared__ float t[32][33];
    const int z = blockIdx.z;
    const float* src = (z == 0) ? wq : (z == 1) ? wk : wv;
    __half* dhi = g_wthi + (size_t)z * 1048576;
    __half* dlo = g_wtlo + (size_t)z * 1048576;
    const int tx = threadIdx.x, ty = threadIdx.y;
    const int x0 = blockIdx.x * 32;  // k
    const int y0 = blockIdx.y * 32;  // n
#pragma unroll
    for (int i = 0; i < 4; ++i)
        t[ty + i * 8][tx] = src[(size_t)(x0 + ty + i * 8) * 1024 + y0 + tx];
    __syncthreads();
#pragma unroll
    for (int i = 0; i < 4; ++i) {
        float v = t[tx][ty + i * 8];
        __half h = __float2half_rn(v);
        dhi[(size_t)(y0 + ty + i * 8) * 1024 + x0 + tx] = h;
        dlo[(size_t)(y0 + ty + i * 8) * 1024 + x0 + tx] =
            __float2half_rn(v - __half2float(h));
    }
}

// ---------------------------------------------------------------------------
// Split-fp16 HMMA GEMM: C(4096x1024) = A @ B^T + bias. 3-term hi/lo split.
// CTA tile 128x128, 128 threads / 4 warps (2x2), warp tile 64x64 (4 m-frags).
// Per 32-k chunk: combined tiles [128 rows][64 halves], cols 0..31 hi / 32..63 lo.
// modes: 0=Q (scale+bias, split out), 1=K (bias, split out),
//        2=V (bias, fp16 out), 3=O (bias, fp32 out)
// ---------------------------------------------------------------------------
#define GC_STAGE 32768   // A 16KB + B 16KB
__global__ __launch_bounds__(128) void gemm_split_kernel(
    const float* __restrict__ bq, const float* __restrict__ bk,
    const float* __restrict__ bv, const float* __restrict__ bo,
    const float* __restrict__ pds, float* __restrict__ out, int mode_base)
{
    extern __shared__ char smem[];
    const int mode = mode_base + blockIdx.z;

    const __half* Ahi = (mode < 3) ? g_xhi : g_ahi;
    const __half* Alo = (mode < 3) ? g_xlo : g_alo;
    const __half* Bhi = (mode < 3) ? g_wthi + (size_t)mode * 1048576 : g_wohi;
    const __half* Blo = (mode < 3) ? g_wtlo + (size_t)mode * 1048576 : g_wolo;
    const float* bias = (mode == 0) ? bq : (mode == 1) ? bk : (mode == 2) ? bv : bo;

    const int tid = threadIdx.x;
    const int wid = tid >> 5, lane = tid & 31;
    const int m0 = (wid & 1) * 64, n0 = (wid >> 1) * 64;
    const int row0 = blockIdx.y * 128, col0 = blockIdx.x * 128;
    const uint32_t sb = smem_u32(smem);
    const int lrow = lane & 15;
    const int lkof = (lane & 16) >> 1;

    // per-thread copy pattern: c8 and r0 constant, r advances 16/it, 8 its each
    const int c8 = (tid & 7) << 3;
    const int r0t = tid >> 3;                 // 0..15
    const int inlo = (c8 >= 32);
    const int kc = c8 & 31;
    const __half* gAb = (inlo ? Alo : Ahi) + (size_t)(row0 + r0t) * 1024 + kc;
    const __half* gBb = (inlo ? Blo : Bhi) + (size_t)(col0 + r0t) * 1024 + kc;
    const uint32_t sOff0 = swz_h(r0t, c8);    // swizzle xor depends on r&7 only; +16r keeps it

    float acc[4][8][4];
#pragma unroll
    for (int i = 0; i < 4; ++i)
#pragma unroll
        for (int j = 0; j < 8; ++j)
#pragma unroll
            for (int c = 0; c < 4; ++c) acc[i][j][c] = 0.f;

    auto issue = [&](int k0, int st) {
        uint32_t a_dst = sb + st * GC_STAGE + sOff0;
        uint32_t b_dst = a_dst + 16384;
#pragma unroll
        for (int it = 0; it < 8; ++it) {
            CP_A16(a_dst + it * (16 * 128), gAb + k0 + (size_t)it * 16 * 1024);
            CP_A16(b_dst + it * (16 * 128), gBb + k0 + (size_t)it * 16 * 1024);
        }
        CP_COMMIT();
    };

    issue(0, 0);
    for (int c = 0; c < 32; ++c) {
        if (c + 1 < 32) { issue((c + 1) * 32, (c + 1) & 1); CP_WAIT1(); }
        else            { CP_WAIT0(); }
        __syncthreads();
        const uint32_t aoff = sb + (c & 1) * GC_STAGE;
        const uint32_t boff = aoff + 16384;
#pragma unroll
        for (int ks = 0; ks < 32; ks += 16) {
            uint32_t afh[4][4], afl[4][4], bf[4][4];
#pragma unroll
            for (int mi = 0; mi < 4; ++mi) {
                ldsm_x4(afh[mi], aoff + swz_h(m0 + mi * 16 + lrow, ks + lkof));       // Ah
                ldsm_x4(afl[mi], aoff + swz_h(m0 + mi * 16 + lrow, ks + 32 + lkof));  // Al
            }
#pragma unroll
            for (int g = 0; g < 4; ++g)
                ldsm_x4(bf[g], boff + swz_h(n0 + g * 16 + lrow, ks + lkof));          // Bh
#pragma unroll
            for (int mi = 0; mi < 4; ++mi)
#pragma unroll
                for (int g = 0; g < 4; ++g) {
                    mma16816(acc[mi][2 * g],     afh[mi], bf[g][0], bf[g][2]);
                    mma16816(acc[mi][2 * g + 1], afh[mi], bf[g][1], bf[g][3]);
                    mma16816(acc[mi][2 * g],     afl[mi], bf[g][0], bf[g][2]);
                    mma16816(acc[mi][2 * g + 1], afl[mi], bf[g][1], bf[g][3]);
                }
#pragma unroll
            for (int g = 0; g < 4; ++g)
                ldsm_x4(bf[g], boff + swz_h(n0 + g * 16 + lrow, ks + 32 + lkof));     // Bl
#pragma unroll
            for (int mi = 0; mi < 4; ++mi)
#pragma unroll
                for (int g = 0; g < 4; ++g) {
                    mma16816(acc[mi][2 * g],     afh[mi], bf[g][0], bf[g][2]);
                    mma16816(acc[mi][2 * g + 1], afh[mi], bf[g][1], bf[g][3]);
                }
        }
        __syncthreads();
    }

    // epilogue
    const int frow = m0 + (lane >> 2);
    const int fcol = n0 + 2 * (lane & 3);
#pragma unroll
    for (int mi = 0; mi < 4; ++mi) {
#pragma unroll
        for (int nj = 0; nj < 8; ++nj) {
            int col = col0 + fcol + nj * 8;
            int r0 = row0 + frow + mi * 16;
            float b0 = bias[col], b1 = bias[col + 1];
            float v0 = acc[mi][nj][0] + b0, v1 = acc[mi][nj][1] + b1;
            float v2 = acc[mi][nj][2] + b0, v3 = acc[mi][nj][3] + b1;
            if (mode == 0) {
                // extra LOG2E folded in so softmax can use raw ex2
                float p0 = pds[col & 63], p1 = pds[(col + 1) & 63];
                float s0 = (LOG2E_ * LOG2E_ * 0.125f) * ((p0 > 20.f) ? p0 : log1pf(__expf(p0)));
                float s1 = (LOG2E_ * LOG2E_ * 0.125f) * ((p1 > 20.f) ? p1 : log1pf(__expf(p1)));
                v0 *= s0; v1 *= s1; v2 *= s0; v3 *= s1;
            }
            if (mode <= 1) {
                __half* Chi = (mode == 0) ? g_qhi : g_khi;
                __half* Clo = (mode == 0) ? g_qlo : g_klo;
                uint32_t h, l;
                split2(v0, v1, h, l);
                *(uint32_t*)&Chi[(size_t)r0 * 1024 + col] = h;
                *(uint32_t*)&Clo[(size_t)r0 * 1024 + col] = l;
                split2(v2, v3, h, l);
                *(uint32_t*)&Chi[(size_t)(r0 + 8) * 1024 + col] = h;
                *(uint32_t*)&Clo[(size_t)(r0 + 8) * 1024 + col] = l;
            } else if (mode == 2) {
                *(uint32_t*)&g_v16[(size_t)r0 * 1024 + col] =
                    pack_h2(__float2half_rn(v0), __float2half_rn(v1));
                *(uint32_t*)&g_v16[(size_t)(r0 + 8) * 1024 + col] =
                    pack_h2(__float2half_rn(v2), __float2half_rn(v3));
            } else {
                *(float2*)&out[(size_t)r0 * 1024 + col] = make_float2(v0, v1);
                *(float2*)&out[(size_t)(r0 + 8) * 1024 + col] = make_float2(v2, v3);
            }
        }
    }
}

// ---------------------------------------------------------------------------
// Flash attention, HMMA (R5 config). Block = (64 q rows, head n, batch b),
// 128 thr / 4 warps, warp owns 16 q rows. QK^T 3-term split; PV split P + fp16 V.
// ex2 softmax (LOG2E prefolded in q scale). Byte mask.
// smem: Qh,Ql [64][64] (16KB) + 2 stages of (Kh,Kl,V [64][64]) (48KB).
// ---------------------------------------------------------------------------
#define A_QOFF 0
#define A_KVOFF 16384
#define A_KVSTAGE 24576
#define ATTN_SMEM (16384 + 2 * 24576)
__global__ __launch_bounds__(128) void attn_hmma_kernel()
{
    extern __shared__ char smem[];
    const int tid = threadIdx.x;
    const int wid = tid >> 5, lane = tid & 31;
    const int q0 = blockIdx.x * 64;
    const int n  = blockIdx.y;
    const int b  = blockIdx.z;
    const uint32_t sb = smem_u32(smem);
    const int lrow = lane & 15;
    const int lkof = (lane & 16) >> 1;

    const size_t gq0 = (size_t)(b * TT + q0) * 1024 + n * 64;

    // prologue: Q hi+lo + KV tile 0 in one cp.async group
#pragma unroll
    for (int it = 0; it < 4; ++it) {
        int idx = it * 128 + tid;           // 0..511
        int r = idx >> 3, k8 = (idx & 7) << 3;
        size_t g = gq0 + (size_t)r * 1024 + k8;
        uint32_t o = swz_h(r, k8);
        CP_A16(sb + A_QOFF + o,        g_qhi + g);
        CP_A16(sb + A_QOFF + 8192 + o, g_qlo + g);
    }
    auto issue_kv = [&](int st, int stage) {
        size_t gk0 = (size_t)(b * TT + st * 64) * 1024 + n * 64;
        uint32_t base = sb + A_KVOFF + stage * A_KVSTAGE;
#pragma unroll
        for (int it = 0; it < 4; ++it) {
            int idx = it * 128 + tid;
            int r = idx >> 3, k8 = (idx & 7) << 3;
            size_t g = gk0 + (size_t)r * 1024 + k8;
            uint32_t o = swz_h(r, k8);
            CP_A16(base + o,         g_khi + g);
            CP_A16(base + 8192 + o,  g_klo + g);
            CP_A16(base + 16384 + o, g_v16 + g);
        }
        CP_COMMIT();
    };
    issue_kv(0, 0);

    uint32_t qh[4][4], ql[4][4];
    float oacc[8][4];
#pragma unroll
    for (int j = 0; j < 8; ++j)
#pragma unroll
        for (int c = 0; c < 4; ++c) oacc[j][c] = 0.f;
    float m_0 = -3.0e38f, m_1 = -3.0e38f, l_0 = 0.f, l_1 = 0.f;

    const int qrl = q0 + wid * 16 + (lane >> 2);
    const int mcol0 = 2 * (lane & 3);
    const unsigned char* mrow0 = g_mask8 + (size_t)(b * TT + qrl) * TT + mcol0;
    const unsigned char* mrow1 = mrow0 + 8 * TT;

    for (int st = 0; st < TT / 64; ++st) {
        if (st + 1 < TT / 64) { issue_kv(st + 1, (st + 1) & 1); CP_WAIT1(); }
        else                  { CP_WAIT0(); }
        __syncthreads();

        if (st == 0) {
#pragma unroll
            for (int kt = 0; kt < 4; ++kt) {
                uint32_t o = swz_h(wid * 16 + lrow, kt * 16 + lkof);
                ldsm_x4(qh[kt], sb + A_QOFF + o);
                ldsm_x4(ql[kt], sb + A_QOFF + 8192 + o);
            }
        }

        const uint32_t kvb = sb + A_KVOFF + (st & 1) * A_KVSTAGE;

        // ---- S = QK^T (3 terms) ----
        float sacc[8][4];
#pragma unroll
        for (int j = 0; j < 8; ++j)
#pragma unroll
            for (int c = 0; c < 4; ++c) sacc[j][c] = 0.f;
#pragma unroll
        for (int kt = 0; kt < 12; ++kt) {
            const int t = kt >> 2, kq = kt & 3;
            const uint32_t* af = (t < 2) ? qh[kq] : ql[kq];
            const uint32_t kb = (t == 1) ? kvb + 8192 : kvb;
            uint32_t bf[4][4];
#pragma unroll
            for (int g = 0; g < 4; ++g)
                ldsm_x4(bf[g], kb + swz_h(g * 16 + lrow, kq * 16 + lkof));
#pragma unroll
            for (int g = 0; g < 4; ++g) {
                mma16816(sacc[2 * g],     af, bf[g][0], bf[g][2]);
                mma16816(sacc[2 * g + 1], af, bf[g][1], bf[g][3]);
            }
        }

        // ---- mask (byte) ----
#pragma unroll
        for (int j = 0; j < 8; ++j) {
            int col = st * 64 + j * 8;
            uchar2 mv0 = *(const uchar2*)(mrow0 + col);
            uchar2 mv1 = *(const uchar2*)(mrow1 + col);
            if (!mv0.x) sacc[j][0] = -1.0e9f;
            if (!mv0.y) sacc[j][1] = -1.0e9f;
            if (!mv1.x) sacc[j][2] = -1.0e9f;
            if (!mv1.y) sacc[j][3] = -1.0e9f;
        }

        // ---- online softmax (log2 domain) ----
        float mx0 = -3.0e38f, mx1 = -3.0e38f;
#pragma unroll
        for (int j = 0; j < 8; ++j) {
            mx0 = fmaxf(mx0, fmaxf(sacc[j][0], sacc[j][1]));
            mx1 = fmaxf(mx1, fmaxf(sacc[j][2], sacc[j][3]));
        }
        mx0 = fmaxf(mx0, __shfl_xor_sync(0xffffffffu, mx0, 1));
        mx0 = fmaxf(mx0, __shfl_xor_sync(0xffffffffu, mx0, 2));
        mx1 = fmaxf(mx1, __shfl_xor_sync(0xffffffffu, mx1, 1));
        mx1 = fmaxf(mx1, __shfl_xor_sync(0xffffffffu, mx1, 2));
        float mn0 = fmaxf(m_0, mx0), mn1 = fmaxf(m_1, mx1);
        float f0 = ex2(m_0 - mn0), f1 = ex2(m_1 - mn1);
        m_0 = mn0; m_1 = mn1;
        float rs0 = 0.f, rs1 = 0.f;
#pragma unroll
        for (int j = 0; j < 8; ++j) {
            sacc[j][0] = ex2(sacc[j][0] - mn0);
            sacc[j][1] = ex2(sacc[j][1] - mn0);
            sacc[j][2] = ex2(sacc[j][2] - mn1);
            sacc[j][3] = ex2(sacc[j][3] - mn1);
            rs0 += sacc[j][0] + sacc[j][1];
            rs1 += sacc[j][2] + sacc[j][3];
        }
        rs0 += __shfl_xor_sync(0xffffffffu, rs0, 1);
        rs0 += __shfl_xor_sync(0xffffffffu, rs0, 2);
        rs1 += __shfl_xor_sync(0xffffffffu, rs1, 1);
        rs1 += __shfl_xor_sync(0xffffffffu, rs1, 2);
        l_0 = l_0 * f0 + rs0;
        l_1 = l_1 * f1 + rs1;
#pragma unroll
        for (int j = 0; j < 8; ++j) {
            oacc[j][0] *= f0; oacc[j][1] *= f0;
            oacc[j][2] *= f1; oacc[j][3] *= f1;
        }

        // ---- O += P V (P split, V fp16) ----
#pragma unroll
        for (int kt = 0; kt < 4; ++kt) {
            uint32_t ph[4], pl[4];
            {
                const float* sA = sacc[2 * kt];
                const float* sB = sacc[2 * kt + 1];
                split2(sA[0], sA[1], ph[0], pl[0]);
                split2(sA[2], sA[3], ph[1], pl[1]);
                split2(sB[0], sB[1], ph[2], pl[2]);
                split2(sB[2], sB[3], ph[3], pl[3]);
            }
            uint32_t vf[4][4];
#pragma unroll
            for (int g = 0; g < 4; ++g)
                ldsm_x4_t(vf[g], kvb + 16384 + swz_h(kt * 16 + lrow, g * 16 + lkof));
#pragma unroll
            for (int g = 0; g < 4; ++g) {
                mma16816(oacc[2 * g],     ph, vf[g][0], vf[g][1]);
                mma16816(oacc[2 * g],     pl, vf[g][0], vf[g][1]);
                mma16816(oacc[2 * g + 1], ph, vf[g][2], vf[g][3]);
                mma16816(oacc[2 * g + 1], pl, vf[g][2], vf[g][3]);
            }
        }
        __syncthreads();
    }

    // ---- epilogue: normalize + split fp16 store ----
    const float inv0 = 1.0f / l_0, inv1 = 1.0f / l_1;
    const size_t m_lo = (size_t)(b * TT + qrl) * 1024 + n * 64;
#pragma unroll
    for (int j = 0; j < 8; ++j) {
        int col = j * 8 + mcol0;
        uint32_t h, l;
        split2(oacc[j][0] * inv0, oacc[j][1] * inv0, h, l);
        *(uint32_t*)&g_ahi[m_lo + col] = h;
        *(uint32_t*)&g_alo[m_lo + col] = l;
        split2(oacc[j][2] * inv1, oacc[j][3] * inv1, h, l);
        *(uint32_t*)&g_ahi[m_lo + 8 * 1024 + col] = h;
        *(uint32_t*)&g_alo[m_lo + 8 * 1024 + col] = l;
    }
}

// ---------------------------------------------------------------------------
// Launch
// ---------------------------------------------------------------------------
extern "C" void kernel_launch(void* const* d_in, const int* in_sizes, int n_in,
                              void* d_out, int out_size)
{
    const float* x    = (const float*)d_in[0];
    const int*   mask = (const int*)  d_in[1];
    const float* wq   = (const float*)d_in[2];
    const float* bq   = (const float*)d_in[3];
    const float* wk   = (const float*)d_in[4];
    const float* bk   = (const float*)d_in[5];
    const float* wv   = (const float*)d_in[6];
    const float* bv   = (const float*)d_in[7];
    const float* wo   = (const float*)d_in[8];
    const float* bo   = (const float*)d_in[9];
    const float* pds  = (const float*)d_in[10];
    float* out = (float*)d_out;

    const int gemm_smem = 2 * GC_STAGE;  // 64KB
    cudaFuncSetAttribute(gemm_split_kernel, cudaFuncAttributeMaxDynamicSharedMemorySize, gemm_smem);
    cudaFuncSetAttribute(attn_hmma_kernel, cudaFuncAttributeMaxDynamicSharedMemorySize, ATTN_SMEM);

    __half *xhi, *xlo, *wohi, *wolo;
    cudaGetSymbolAddress((void**)&xhi, g_xhi);
    cudaGetSymbolAddress((void**)&xlo, g_xlo);
    cudaGetSymbolAddress((void**)&wohi, g_wohi);
    cudaGetSymbolAddress((void**)&wolo, g_wolo);

    split_kernel<<<4096, 256>>>(x, xhi, xlo, 1048576);
    split_kernel<<<1024, 256>>>(wo, wohi, wolo, 262144);
    mask_pack_kernel<<<8192, 256>>>(mask);
    transpose_split_kernel<<<dim3(32, 32, 3), dim3(32, 8)>>>(wq, wk, wv);

    gemm_split_kernel<<<dim3(8, 32, 3), 128, gemm_smem>>>(bq, bk, bv, bo, pds, out, 0);
    attn_hmma_kernel<<<dim3(32, 16, 2), 128, ATTN_SMEM>>>();
    gemm_split_kernel<<<dim3(8, 32, 1), 128, gemm_smem>>>(bq, bk, bv, bo, pds, out, 3);
}

// round 9
// speedup vs baseline: 1.2943x; 1.1534x over previous
#include <cuda_runtime.h>
#include <cuda_fp16.h>
#include <math.h>
#include <cstdint>

#define BB 2
#define TT 2048
#define DD 1024
#define NH 16
#define HD 64
#define LOG2E_ 1.442695041f

// ---------------------------------------------------------------------------
// Scratch (__device__ globals, allocation-free rule)
// ---------------------------------------------------------------------------
__device__ __half g_xhi[4194304], g_xlo[4194304];        // X split       [4096][1024]
__device__ __half g_wthi[3145728], g_wtlo[3145728];      // wq/wk/wv^T    [3][1024 n][1024 k]
__device__ __half g_wohi[1048576], g_wolo[1048576];      // wo split      [1024 d][1024 k]
__device__ __half g_qhi[4194304], g_qlo[4194304];        // q (scaled)    [4096][1024]
__device__ __half g_khi[4194304], g_klo[4194304];        // k             [4096][1024]
__device__ __half g_v16[4194304];                        // v fp16        [4096][1024]
__device__ __half g_ahi[4194304], g_alo[4194304];        // attn out      [4096][1024]
__device__ unsigned char g_mask8[8388608];               // mask bytes    [2][2048][2048]

// ---------------------------------------------------------------------------
// PTX helpers
// ---------------------------------------------------------------------------
__device__ __forceinline__ uint32_t smem_u32(const void* p) {
    uint32_t a;
    asm("{ .reg .u64 t; cvta.to.shared.u64 t, %1; cvt.u32.u64 %0, t; }" : "=r"(a) : "l"(p));
    return a;
}
__device__ __forceinline__ void ldsm_x4(uint32_t* r, uint32_t a) {
    asm volatile("ldmatrix.sync.aligned.m8n8.x4.shared.b16 {%0,%1,%2,%3}, [%4];"
                 : "=r"(r[0]), "=r"(r[1]), "=r"(r[2]), "=r"(r[3]) : "r"(a));
}
__device__ __forceinline__ void ldsm_x4_t(uint32_t* r, uint32_t a) {
    asm volatile("ldmatrix.sync.aligned.m8n8.x4.trans.shared.b16 {%0,%1,%2,%3}, [%4];"
                 : "=r"(r[0]), "=r"(r[1]), "=r"(r[2]), "=r"(r[3]) : "r"(a));
}
__device__ __forceinline__ void mma16816(float* c, const uint32_t* a, uint32_t b0, uint32_t b1) {
    asm volatile(
        "mma.sync.aligned.m16n8k16.row.col.f32.f16.f16.f32 "
        "{%0,%1,%2,%3}, {%4,%5,%6,%7}, {%8,%9}, {%0,%1,%2,%3};"
        : "+f"(c[0]), "+f"(c[1]), "+f"(c[2]), "+f"(c[3])
        : "r"(a[0]), "r"(a[1]), "r"(a[2]), "r"(a[3]), "r"(b0), "r"(b1));
}
#define CP_A16(dst, src) \
    asm volatile("cp.async.cg.shared.global [%0], [%1], 16;" :: "r"(dst), "l"(src))
#define CP_COMMIT() asm volatile("cp.async.commit_group;" ::: "memory")
#define CP_WAIT0()  asm volatile("cp.async.wait_group 0;" ::: "memory")
#define CP_WAIT1()  asm volatile("cp.async.wait_group 1;" ::: "memory")

__device__ __forceinline__ float ex2(float x) {
    float y;
    asm("ex2.approx.ftz.f32 %0, %1;" : "=f"(y) : "f"(x));
    return y;
}

// swizzled byte offset, 64-half (128B) rows
__device__ __forceinline__ uint32_t swz_h(int r, int k) {
    return (uint32_t)(r * 128 + (((k >> 3) ^ (r & 7)) << 4) + ((k & 7) << 1));
}
__device__ __forceinline__ uint32_t pack_h2(__half a, __half b) {
    __half2 h = __halves2half2(a, b);
    return *(uint32_t*)&h;
}
__device__ __forceinline__ void split2(float x, float y, uint32_t& hi, uint32_t& lo) {
    __half hx = __float2half_rn(x), hy = __float2half_rn(y);
    hi = pack_h2(hx, hy);
    lo = pack_h2(__float2half_rn(x - __half2float(hx)),
                 __float2half_rn(y - __half2float(hy)));
}

// ---------------------------------------------------------------------------
// Preprocess kernels
// ---------------------------------------------------------------------------
__global__ __launch_bounds__(256) void split_kernel(
    const float* __restrict__ src, __half* __restrict__ hi, __half* __restrict__ lo, int n4)
{
    int i = blockIdx.x * 256 + threadIdx.x;
    if (i >= n4) return;
    float4 v = *(const float4*)&src[i * 4];
    uint32_t h0, l0, h1, l1;
    split2(v.x, v.y, h0, l0);
    split2(v.z, v.w, h1, l1);
    *(uint32_t*)&hi[i * 4] = h0; *(uint32_t*)&hi[i * 4 + 2] = h1;
    *(uint32_t*)&lo[i * 4] = l0; *(uint32_t*)&lo[i * 4 + 2] = l1;
}

// 2*2048*2048 = 8388608 ints -> 2097152 int4 -> 8192 blocks of 256
__global__ __launch_bounds__(256) void mask_pack_kernel(const int* __restrict__ m)
{
    int i = blockIdx.x * 256 + threadIdx.x;
    int4 v = *(const int4*)&m[i * 4];
    uchar4 o;
    o.x = (unsigned char)v.x; o.y = (unsigned char)v.y;
    o.z = (unsigned char)v.z; o.w = (unsigned char)v.w;
    *(uchar4*)&g_mask8[i * 4] = o;
}

__global__ __launch_bounds__(256) void transpose_split_kernel(
    const float* __restrict__ wq, const float* __restrict__ wk, const float* __restrict__ wv)
{
    __shared__ float t[32][33];
    const int z = blockIdx.z;
    const float* src = (z == 0) ? wq : (z == 1) ? wk : wv;
    __half* dhi = g_wthi + (size_t)z * 1048576;
    __half* dlo = g_wtlo + (size_t)z * 1048576;
    const int tx = threadIdx.x, ty = threadIdx.y;
    const int x0 = blockIdx.x * 32;  // k
    const int y0 = blockIdx.y * 32;  // n
#pragma unroll
    for (int i = 0; i < 4; ++i)
        t[ty + i * 8][tx] = src[(size_t)(x0 + ty + i * 8) * 1024 + y0 + tx];
    __syncthreads();
#pragma unroll
    for (int i = 0; i < 4; ++i) {
        float v = t[tx][ty + i * 8];
        __half h = __float2half_rn(v);
        dhi[(size_t)(y0 + ty + i * 8) * 1024 + x0 + tx] = h;
        dlo[(size_t)(y0 + ty + i * 8) * 1024 + x0 + tx] =
            __float2half_rn(v - __half2float(h));
    }
}

// ---------------------------------------------------------------------------
// Split-fp16 HMMA GEMM (R5-proven shape): C(4096x1024) = A @ B^T + bias.
// Term chunks of K=32: t0=Ah*Bh, t1=Ah*Bl, t2=Al*Bh.
// Q,K modes: 3 terms (48 chunks). V,O modes: 2 terms (32 chunks) — their
// error stays linear downstream, 2^-12 rel is safe.
// 256 thr, 8 warps (4m x 2n), warp tile 32x64, CTA tile 128x128.
// ---------------------------------------------------------------------------
#define G_STAGE 16384
__global__ __launch_bounds__(256, 2) void gemm_split_kernel(
    const float* __restrict__ bq, const float* __restrict__ bk,
    const float* __restrict__ bv, const float* __restrict__ bo,
    const float* __restrict__ pds, float* __restrict__ out, int mode_base)
{
    extern __shared__ char smem[];
    const int mode = mode_base + blockIdx.z;

    const __half* Ahi = (mode < 3) ? g_xhi : g_ahi;
    const __half* Alo = (mode < 3) ? g_xlo : g_alo;
    const __half* Bhi = (mode < 3) ? g_wthi + (size_t)mode * 1048576 : g_wohi;
    const __half* Blo = (mode < 3) ? g_wtlo + (size_t)mode * 1048576 : g_wolo;
    const float* bias = (mode == 0) ? bq : (mode == 1) ? bk : (mode == 2) ? bv : bo;
    const int nch = (mode <= 1) ? 48 : 32;   // 3 terms vs 2 terms

    const int tid = threadIdx.x;
    const int wid = tid >> 5, lane = tid & 31;
    const int m0 = (wid & 3) * 32, n0 = (wid >> 2) * 64;
    const int row0 = blockIdx.y * 128, col0 = blockIdx.x * 128;
    const uint32_t sbA = smem_u32(smem);
    const uint32_t sbB = sbA + 2 * G_STAGE;
    const int lrow = lane & 15;
    const int lkof = (lane & 16) >> 1;

    float acc[2][8][4];
#pragma unroll
    for (int i = 0; i < 2; ++i)
#pragma unroll
        for (int j = 0; j < 8; ++j)
#pragma unroll
            for (int c = 0; c < 4; ++c) acc[i][j][c] = 0.f;

    auto issue = [&](int c, int st) {
        int t = c >> 4, k0 = (c & 15) << 5;
        const __half* Ap = (t < 2) ? Ahi : Alo;
        const __half* Bp = (t == 1) ? Blo : Bhi;
#pragma unroll
        for (int it = 0; it < 4; ++it) {
            int idx = it * 256 + tid;
            int r = idx >> 3, k8 = (idx & 7) << 3;
            // tile row layout: [128 rows][64 halves] = two 32-k chunks? No:
            // one 32-k chunk per stage is 128*32*2 = 8KB; we use 64-half rows
            // covering k8 in 0..63 => read TWO 32-k chunks? Keep R5 exact:
            // R5 loaded 64-k per stage per term by using k0=(c&15)<<6 with 16
            // chunks per term of 64k. Restore that:
            (void)r; (void)k8;
        }
        // R5-exact body below (replaces the loop above)
        {
            int k0b = (c & 15) << 6;
#pragma unroll
            for (int it = 0; it < 2; ++it) {
                int idx = it * 256 + tid;         // 0..511 -> 16B units of 8KB? 
                (void)idx; (void)k0b;
            }
        }
        CP_COMMIT();
        (void)k0; (void)st;
    };
    (void)issue;

    // ---- R5-exact copy/compute loop (restored verbatim) ----
    auto issue5 = [&](int c, int st) {
        int t = c >> 4, k0 = (c & 15) << 6;
        const __half* Ap = (t < 2) ? Ahi : Alo;
        const __half* Bp = (t == 1) ? Blo : Bhi;
#pragma unroll
        for (int it = 0; it < 4; ++it) {
            int idx = it * 256 + tid;
            int r = idx >> 3, k8 = (idx & 7) << 3;
            CP_A16(sbA + st * G_STAGE + swz_h(r, k8),
                   Ap + (size_t)(row0 + r) * 1024 + k0 + k8);
            CP_A16(sbB + st * G_STAGE + swz_h(r, k8),
                   Bp + (size_t)(col0 + r) * 1024 + k0 + k8);
        }
        CP_COMMIT();
    };

    issue5(0, 0);
    for (int c = 0; c < nch; ++c) {
        if (c + 1 < nch) { issue5(c + 1, (c + 1) & 1); CP_WAIT1(); }
        else             { CP_WAIT0(); }
        __syncthreads();
        const uint32_t aoff = sbA + (c & 1) * G_STAGE;
        const uint32_t boff = sbB + (c & 1) * G_STAGE;
#pragma unroll
        for (int kk = 0; kk < 64; kk += 16) {
            uint32_t af[2][4], bf[4][4];
#pragma unroll
            for (int mi = 0; mi < 2; ++mi)
                ldsm_x4(af[mi], aoff + swz_h(m0 + mi * 16 + lrow, kk + lkof));
#pragma unroll
            for (int g = 0; g < 4; ++g)
                ldsm_x4(bf[g], boff + swz_h(n0 + g * 16 + lrow, kk + lkof));
#pragma unroll
            for (int mi = 0; mi < 2; ++mi)
#pragma unroll
                for (int g = 0; g < 4; ++g) {
                    mma16816(acc[mi][2 * g],     af[mi], bf[g][0], bf[g][2]);
                    mma16816(acc[mi][2 * g + 1], af[mi], bf[g][1], bf[g][3]);
                }
        }
        __syncthreads();
    }

    // epilogue
    const int frow = m0 + (lane >> 2);
    const int fcol = n0 + 2 * (lane & 3);
#pragma unroll
    for (int mi = 0; mi < 2; ++mi) {
#pragma unroll
        for (int nj = 0; nj < 8; ++nj) {
            int col = col0 + fcol + nj * 8;
            int r0 = row0 + frow + mi * 16;
            float b0 = bias[col], b1 = bias[col + 1];
            float v0 = acc[mi][nj][0] + b0, v1 = acc[mi][nj][1] + b1;
            float v2 = acc[mi][nj][2] + b0, v3 = acc[mi][nj][3] + b1;
            if (mode == 0) {
                // extra LOG2E folded in so softmax can use raw ex2
                float p0 = pds[col & 63], p1 = pds[(col + 1) & 63];
                float s0 = (LOG2E_ * LOG2E_ * 0.125f) * ((p0 > 20.f) ? p0 : log1pf(__expf(p0)));
                float s1 = (LOG2E_ * LOG2E_ * 0.125f) * ((p1 > 20.f) ? p1 : log1pf(__expf(p1)));
                v0 *= s0; v1 *= s1; v2 *= s0; v3 *= s1;
            }
            if (mode <= 1) {
                __half* Chi = (mode == 0) ? g_qhi : g_khi;
                __half* Clo = (mode == 0) ? g_qlo : g_klo;
                uint32_t h, l;
                split2(v0, v1, h, l);
                *(uint32_t*)&Chi[(size_t)r0 * 1024 + col] = h;
                *(uint32_t*)&Clo[(size_t)r0 * 1024 + col] = l;
                split2(v2, v3, h, l);
                *(uint32_t*)&Chi[(size_t)(r0 + 8) * 1024 + col] = h;
                *(uint32_t*)&Clo[(size_t)(r0 + 8) * 1024 + col] = l;
            } else if (mode == 2) {
                *(uint32_t*)&g_v16[(size_t)r0 * 1024 + col] =
                    pack_h2(__float2half_rn(v0), __float2half_rn(v1));
                *(uint32_t*)&g_v16[(size_t)(r0 + 8) * 1024 + col] =
                    pack_h2(__float2half_rn(v2), __float2half_rn(v3));
            } else {
                *(float2*)&out[(size_t)r0 * 1024 + col] = make_float2(v0, v1);
                *(float2*)&out[(size_t)(r0 + 8) * 1024 + col] = make_float2(v2, v3);
            }
        }
    }
}

// ---------------------------------------------------------------------------
// Flash attention, HMMA (R5 config + byte mask + ex2). Block = (64 q rows,
// head n, batch b), 128 thr / 4 warps. QK^T 3-term split; PV split P + fp16 V.
// smem: Qh,Ql [64][64] (16KB) + 2 stages of (Kh,Kl,V [64][64]) (48KB).
// ---------------------------------------------------------------------------
#define A_QOFF 0
#define A_KVOFF 16384
#define A_KVSTAGE 24576
#define ATTN_SMEM (16384 + 2 * 24576)
__global__ __launch_bounds__(128) void attn_hmma_kernel()
{
    extern __shared__ char smem[];
    const int tid = threadIdx.x;
    const int wid = tid >> 5, lane = tid & 31;
    const int q0 = blockIdx.x * 64;
    const int n  = blockIdx.y;
    const int b  = blockIdx.z;
    const uint32_t sb = smem_u32(smem);
    const int lrow = lane & 15;
    const int lkof = (lane & 16) >> 1;

    const size_t gq0 = (size_t)(b * TT + q0) * 1024 + n * 64;

#pragma unroll
    for (int it = 0; it < 4; ++it) {
        int idx = it * 128 + tid;
        int r = idx >> 3, k8 = (idx & 7) << 3;
        size_t g = gq0 + (size_t)r * 1024 + k8;
        uint32_t o = swz_h(r, k8);
        CP_A16(sb + A_QOFF + o,        g_qhi + g);
        CP_A16(sb + A_QOFF + 8192 + o, g_qlo + g);
    }
    auto issue_kv = [&](int st, int stage) {
        size_t gk0 = (size_t)(b * TT + st * 64) * 1024 + n * 64;
        uint32_t base = sb + A_KVOFF + stage * A_KVSTAGE;
#pragma unroll
        for (int it = 0; it < 4; ++it) {
            int idx = it * 128 + tid;
            int r = idx >> 3, k8 = (idx & 7) << 3;
            size_t g = gk0 + (size_t)r * 1024 + k8;
            uint32_t o = swz_h(r, k8);
            CP_A16(base + o,         g_khi + g);
            CP_A16(base + 8192 + o,  g_klo + g);
            CP_A16(base + 16384 + o, g_v16 + g);
        }
        CP_COMMIT();
    };
    issue_kv(0, 0);

    uint32_t qh[4][4], ql[4][4];
    float oacc[8][4];
#pragma unroll
    for (int j = 0; j < 8; ++j)
#pragma unroll
        for (int c = 0; c < 4; ++c) oacc[j][c] = 0.f;
    float m_0 = -3.0e38f, m_1 = -3.0e38f, l_0 = 0.f, l_1 = 0.f;

    const int qrl = q0 + wid * 16 + (lane >> 2);
    const int mcol0 = 2 * (lane & 3);
    const unsigned char* mrow0 = g_mask8 + (size_t)(b * TT + qrl) * TT + mcol0;
    const unsigned char* mrow1 = mrow0 + 8 * TT;

    for (int st = 0; st < TT / 64; ++st) {
        if (st + 1 < TT / 64) { issue_kv(st + 1, (st + 1) & 1); CP_WAIT1(); }
        else                  { CP_WAIT0(); }
        __syncthreads();

        if (st == 0) {
#pragma unroll
            for (int kt = 0; kt < 4; ++kt) {
                uint32_t o = swz_h(wid * 16 + lrow, kt * 16 + lkof);
                ldsm_x4(qh[kt], sb + A_QOFF + o);
                ldsm_x4(ql[kt], sb + A_QOFF + 8192 + o);
            }
        }

        const uint32_t kvb = sb + A_KVOFF + (st & 1) * A_KVSTAGE;

        // ---- S = QK^T (3 terms) ----
        float sacc[8][4];
#pragma unroll
        for (int j = 0; j < 8; ++j)
#pragma unroll
            for (int c = 0; c < 4; ++c) sacc[j][c] = 0.f;
#pragma unroll
        for (int kt = 0; kt < 12; ++kt) {
            const int t = kt >> 2, kq = kt & 3;
            const uint32_t* af = (t < 2) ? qh[kq] : ql[kq];
            const uint32_t kb = (t == 1) ? kvb + 8192 : kvb;
            uint32_t bf[4][4];
#pragma unroll
            for (int g = 0; g < 4; ++g)
                ldsm_x4(bf[g], kb + swz_h(g * 16 + lrow, kq * 16 + lkof));
#pragma unroll
            for (int g = 0; g < 4; ++g) {
                mma16816(sacc[2 * g],     af, bf[g][0], bf[g][2]);
                mma16816(sacc[2 * g + 1], af, bf[g][1], bf[g][3]);
            }
        }

        // ---- mask (byte) ----
#pragma unroll
        for (int j = 0; j < 8; ++j) {
            int col = st * 64 + j * 8;
            uchar2 mv0 = *(const uchar2*)(mrow0 + col);
            uchar2 mv1 = *(const uchar2*)(mrow1 + col);
            if (!mv0.x) sacc[j][0] = -1.0e9f;
            if (!mv0.y) sacc[j][1] = -1.0e9f;
            if (!mv1.x) sacc[j][2] = -1.0e9f;
            if (!mv1.y) sacc[j][3] = -1.0e9f;
        }

        // ---- online softmax (log2 domain) ----
        float mx0 = -3.0e38f, mx1 = -3.0e38f;
#pragma unroll
        for (int j = 0; j < 8; ++j) {
            mx0 = fmaxf(mx0, fmaxf(sacc[j][0], sacc[j][1]));
            mx1 = fmaxf(mx1, fmaxf(sacc[j][2], sacc[j][3]));
        }
        mx0 = fmaxf(mx0, __shfl_xor_sync(0xffffffffu, mx0, 1));
        mx0 = fmaxf(mx0, __shfl_xor_sync(0xffffffffu, mx0, 2));
        mx1 = fmaxf(mx1, __shfl_xor_sync(0xffffffffu, mx1, 1));
        mx1 = fmaxf(mx1, __shfl_xor_sync(0xffffffffu, mx1, 2));
        float mn0 = fmaxf(m_0, mx0), mn1 = fmaxf(m_1, mx1);
        float f0 = ex2(m_0 - mn0), f1 = ex2(m_1 - mn1);
        m_0 = mn0; m_1 = mn1;
        float rs0 = 0.f, rs1 = 0.f;
#pragma unroll
        for (int j = 0; j < 8; ++j) {
            sacc[j][0] = ex2(sacc[j][0] - mn0);
            sacc[j][1] = ex2(sacc[j][1] - mn0);
            sacc[j][2] = ex2(sacc[j][2] - mn1);
            sacc[j][3] = ex2(sacc[j][3] - mn1);
            rs0 += sacc[j][0] + sacc[j][1];
            rs1 += sacc[j][2] + sacc[j][3];
        }
        rs0 += __shfl_xor_sync(0xffffffffu, rs0, 1);
        rs0 += __shfl_xor_sync(0xffffffffu, rs0, 2);
        rs1 += __shfl_xor_sync(0xffffffffu, rs1, 1);
        rs1 += __shfl_xor_sync(0xffffffffu, rs1, 2);
        l_0 = l_0 * f0 + rs0;
        l_1 = l_1 * f1 + rs1;
#pragma unroll
        for (int j = 0; j < 8; ++j) {
            oacc[j][0] *= f0; oacc[j][1] *= f0;
            oacc[j][2] *= f1; oacc[j][3] *= f1;
        }

        // ---- O += P V (P split, V fp16) ----
#pragma unroll
        for (int kt = 0; kt < 4; ++kt) {
            uint32_t ph[4], pl[4];
            {
                const float* sA = sacc[2 * kt];
                const float* sB = sacc[2 * kt + 1];
                split2(sA[0], sA[1], ph[0], pl[0]);
                split2(sA[2], sA[3], ph[1], pl[1]);
                split2(sB[0], sB[1], ph[2], pl[2]);
                split2(sB[2], sB[3], ph[3], pl[3]);
            }
            uint32_t vf[4][4];
#pragma unroll
            for (int g = 0; g < 4; ++g)
                ldsm_x4_t(vf[g], kvb + 16384 + swz_h(kt * 16 + lrow, g * 16 + lkof));
#pragma unroll
            for (int g = 0; g < 4; ++g) {
                mma16816(oacc[2 * g],     ph, vf[g][0], vf[g][1]);
                mma16816(oacc[2 * g],     pl, vf[g][0], vf[g][1]);
                mma16816(oacc[2 * g + 1], ph, vf[g][2], vf[g][3]);
                mma16816(oacc[2 * g + 1], pl, vf[g][2], vf[g][3]);
            }
        }
        __syncthreads();
    }

    // ---- epilogue: normalize + split fp16 store ----
    const float inv0 = 1.0f / l_0, inv1 = 1.0f / l_1;
    const size_t m_lo = (size_t)(b * TT + qrl) * 1024 + n * 64;
#pragma unroll
    for (int j = 0; j < 8; ++j) {
        int col = j * 8 + mcol0;
        uint32_t h, l;
        split2(oacc[j][0] * inv0, oacc[j][1] * inv0, h, l);
        *(uint32_t*)&g_ahi[m_lo + col] = h;
        *(uint32_t*)&g_alo[m_lo + col] = l;
        split2(oacc[j][2] * inv1, oacc[j][3] * inv1, h, l);
        *(uint32_t*)&g_ahi[m_lo + 8 * 1024 + col] = h;
        *(uint32_t*)&g_alo[m_lo + 8 * 1024 + col] = l;
    }
}

// ---------------------------------------------------------------------------
// Launch
// ---------------------------------------------------------------------------
extern "C" void kernel_launch(void* const* d_in, const int* in_sizes, int n_in,
                              void* d_out, int out_size)
{
    const float* x    = (const float*)d_in[0];
    const int*   mask = (const int*)  d_in[1];
    const float* wq   = (const float*)d_in[2];
    const float* bq   = (const float*)d_in[3];
    const float* wk   = (const float*)d_in[4];
    const float* bk   = (const float*)d_in[5];
    const float* wv   = (const float*)d_in[6];
    const float* bv   = (const float*)d_in[7];
    const float* wo   = (const float*)d_in[8];
    const float* bo   = (const float*)d_in[9];
    const float* pds  = (const float*)d_in[10];
    float* out = (float*)d_out;

    const int gemm_smem = 4 * G_STAGE;  // 64KB
    cudaFuncSetAttribute(gemm_split_kernel, cudaFuncAttributeMaxDynamicSharedMemorySize, gemm_smem);
    cudaFuncSetAttribute(attn_hmma_kernel, cudaFuncAttributeMaxDynamicSharedMemorySize, ATTN_SMEM);

    __half *xhi, *xlo, *wohi, *wolo;
    cudaGetSymbolAddress((void**)&xhi, g_xhi);
    cudaGetSymbolAddress((void**)&xlo, g_xlo);
    cudaGetSymbolAddress((void**)&wohi, g_wohi);
    cudaGetSymbolAddress((void**)&wolo, g_wolo);

    split_kernel<<<4096, 256>>>(x, xhi, xlo, 1048576);
    split_kernel<<<1024, 256>>>(wo, wohi, wolo, 262144);
    mask_pack_kernel<<<8192, 256>>>(mask);
    transpose_split_kernel<<<dim3(32, 32, 3), dim3(32, 8)>>>(wq, wk, wv);

    gemm_split_kernel<<<dim3(8, 32, 3), 256, gemm_smem>>>(bq, bk, bv, bo, pds, out, 0);
    attn_hmma_kernel<<<dim3(32, 16, 2), 128, ATTN_SMEM>>>();
    gemm_split_kernel<<<dim3(8, 32, 1), 256, gemm_smem>>>(bq, bk, bv, bo, pds, out, 3);
}

// round 10
// speedup vs baseline: 1.3632x; 1.0532x over previous
#include <cuda_runtime.h>
#include <cuda_fp16.h>
#include <math.h>
#include <cstdint>

#define BB 2
#define TT 2048
#define DD 1024
#define NH 16
#define HD 64
#define LOG2E_ 1.442695041f

// ---------------------------------------------------------------------------
// Scratch (__device__ globals, allocation-free rule)
// ---------------------------------------------------------------------------
__device__ __half g_xhi[4194304], g_xlo[4194304];        // X split       [4096][1024]
__device__ __half g_wthi[3145728], g_wtlo[3145728];      // wq/wk/wv^T    [3][1024 n][1024 k]
__device__ __half g_wohi[1048576], g_wolo[1048576];      // wo split      [1024 d][1024 k]
__device__ __half g_qhi[4194304], g_qlo[4194304];        // q (scaled)    [4096][1024]
__device__ __half g_khi[4194304], g_klo[4194304];        // k             [4096][1024]
__device__ __half g_v16[4194304];                        // v fp16        [4096][1024]
__device__ __half g_ahi[4194304];                        // attn out hi   [4096][1024]
__device__ unsigned char g_mask8[8388608];               // mask bytes    [2][2048][2048]

// ---------------------------------------------------------------------------
// PTX helpers
// ---------------------------------------------------------------------------
__device__ __forceinline__ uint32_t smem_u32(const void* p) {
    uint32_t a;
    asm("{ .reg .u64 t; cvta.to.shared.u64 t, %1; cvt.u32.u64 %0, t; }" : "=r"(a) : "l"(p));
    return a;
}
__device__ __forceinline__ void ldsm_x4(uint32_t* r, uint32_t a) {
    asm volatile("ldmatrix.sync.aligned.m8n8.x4.shared.b16 {%0,%1,%2,%3}, [%4];"
                 : "=r"(r[0]), "=r"(r[1]), "=r"(r[2]), "=r"(r[3]) : "r"(a));
}
__device__ __forceinline__ void ldsm_x4_t(uint32_t* r, uint32_t a) {
    asm volatile("ldmatrix.sync.aligned.m8n8.x4.trans.shared.b16 {%0,%1,%2,%3}, [%4];"
                 : "=r"(r[0]), "=r"(r[1]), "=r"(r[2]), "=r"(r[3]) : "r"(a));
}
__device__ __forceinline__ void mma16816(float* c, const uint32_t* a, uint32_t b0, uint32_t b1) {
    asm volatile(
        "mma.sync.aligned.m16n8k16.row.col.f32.f16.f16.f32 "
        "{%0,%1,%2,%3}, {%4,%5,%6,%7}, {%8,%9}, {%0,%1,%2,%3};"
        : "+f"(c[0]), "+f"(c[1]), "+f"(c[2]), "+f"(c[3])
        : "r"(a[0]), "r"(a[1]), "r"(a[2]), "r"(a[3]), "r"(b0), "r"(b1));
}
#define CP_A16(dst, src) \
    asm volatile("cp.async.cg.shared.global [%0], [%1], 16;" :: "r"(dst), "l"(src))
#define CP_COMMIT() asm volatile("cp.async.commit_group;" ::: "memory")
#define CP_WAIT0()  asm volatile("cp.async.wait_group 0;" ::: "memory")
#define CP_WAIT1()  asm volatile("cp.async.wait_group 1;" ::: "memory")

__device__ __forceinline__ float ex2(float x) {
    float y;
    asm("ex2.approx.ftz.f32 %0, %1;" : "=f"(y) : "f"(x));
    return y;
}

// swizzled byte offset, 64-half (128B) rows
__device__ __forceinline__ uint32_t swz_h(int r, int k) {
    return (uint32_t)(r * 128 + (((k >> 3) ^ (r & 7)) << 4) + ((k & 7) << 1));
}
__device__ __forceinline__ uint32_t pack_h2(__half a, __half b) {
    __half2 h = __halves2half2(a, b);
    return *(uint32_t*)&h;
}
__device__ __forceinline__ void split2(float x, float y, uint32_t& hi, uint32_t& lo) {
    __half hx = __float2half_rn(x), hy = __float2half_rn(y);
    hi = pack_h2(hx, hy);
    lo = pack_h2(__float2half_rn(x - __half2float(hx)),
                 __float2half_rn(y - __half2float(hy)));
}

// ---------------------------------------------------------------------------
// Preprocess kernels
// ---------------------------------------------------------------------------
__global__ __launch_bounds__(256) void split_kernel(
    const float* __restrict__ src, __half* __restrict__ hi, __half* __restrict__ lo, int n4)
{
    int i = blockIdx.x * 256 + threadIdx.x;
    if (i >= n4) return;
    float4 v = *(const float4*)&src[i * 4];
    uint32_t h0, l0, h1, l1;
    split2(v.x, v.y, h0, l0);
    split2(v.z, v.w, h1, l1);
    *(uint32_t*)&hi[i * 4] = h0; *(uint32_t*)&hi[i * 4 + 2] = h1;
    *(uint32_t*)&lo[i * 4] = l0; *(uint32_t*)&lo[i * 4 + 2] = l1;
}

// 2*2048*2048 = 8388608 ints -> 2097152 int4 -> 8192 blocks of 256
__global__ __launch_bounds__(256) void mask_pack_kernel(const int* __restrict__ m)
{
    int i = blockIdx.x * 256 + threadIdx.x;
    int4 v = *(const int4*)&m[i * 4];
    uchar4 o;
    o.x = (unsigned char)v.x; o.y = (unsigned char)v.y;
    o.z = (unsigned char)v.z; o.w = (unsigned char)v.w;
    *(uchar4*)&g_mask8[i * 4] = o;
}

__global__ __launch_bounds__(256) void transpose_split_kernel(
    const float* __restrict__ wq, const float* __restrict__ wk, const float* __restrict__ wv)
{
    __shared__ float t[32][33];
    const int z = blockIdx.z;
    const float* src = (z == 0) ? wq : (z == 1) ? wk : wv;
    __half* dhi = g_wthi + (size_t)z * 1048576;
    __half* dlo = g_wtlo + (size_t)z * 1048576;
    const int tx = threadIdx.x, ty = threadIdx.y;
    const int x0 = blockIdx.x * 32;  // k
    const int y0 = blockIdx.y * 32;  // n
#pragma unroll
    for (int i = 0; i < 4; ++i)
        t[ty + i * 8][tx] = src[(size_t)(x0 + ty + i * 8) * 1024 + y0 + tx];
    __syncthreads();
#pragma unroll
    for (int i = 0; i < 4; ++i) {
        float v = t[tx][ty + i * 8];
        __half h = __float2half_rn(v);
        dhi[(size_t)(y0 + ty + i * 8) * 1024 + x0 + tx] = h;
        dlo[(size_t)(y0 + ty + i * 8) * 1024 + x0 + tx] =
            __float2half_rn(v - __half2float(h));
    }
}

// ---------------------------------------------------------------------------
// Split-fp16 HMMA GEMM (R5-proven shape): C(4096x1024) = A @ B^T + bias.
// 64-k chunks; term t: t0=Ah*Bh, t1=Ah*Bl, t2=Al*Bh.
// Q,K modes: 3 terms (48 chunks). V,O modes: 2 terms (32 chunks).
// 256 thr, 8 warps (4m x 2n), warp tile 32x64, CTA tile 128x128.
// ---------------------------------------------------------------------------
#define G_STAGE 16384
__global__ __launch_bounds__(256, 2) void gemm_split_kernel(
    const float* __restrict__ bq, const float* __restrict__ bk,
    const float* __restrict__ bv, const float* __restrict__ bo,
    const float* __restrict__ pds, float* __restrict__ out, int mode_base)
{
    extern __shared__ char smem[];
    const int mode = mode_base + blockIdx.z;

    const __half* Ahi = (mode < 3) ? g_xhi : g_ahi;
    const __half* Alo = (mode < 3) ? g_xlo : g_ahi;   // Alo unused when nch==32
    if (mode < 3) Alo = g_xlo;
    const __half* Bhi = (mode < 3) ? g_wthi + (size_t)mode * 1048576 : g_wohi;
    const __half* Blo = (mode < 3) ? g_wtlo + (size_t)mode * 1048576 : g_wolo;
    const float* bias = (mode == 0) ? bq : (mode == 1) ? bk : (mode == 2) ? bv : bo;
    const int nch = (mode <= 1) ? 48 : 32;   // 3 terms vs 2 terms

    const int tid = threadIdx.x;
    const int wid = tid >> 5, lane = tid & 31;
    const int m0 = (wid & 3) * 32, n0 = (wid >> 2) * 64;
    const int row0 = blockIdx.y * 128, col0 = blockIdx.x * 128;
    const uint32_t sbA = smem_u32(smem);
    const uint32_t sbB = sbA + 2 * G_STAGE;
    const int lrow = lane & 15;
    const int lkof = (lane & 16) >> 1;

    float acc[2][8][4];
#pragma unroll
    for (int i = 0; i < 2; ++i)
#pragma unroll
        for (int j = 0; j < 8; ++j)
#pragma unroll
            for (int c = 0; c < 4; ++c) acc[i][j][c] = 0.f;

    auto issue = [&](int c, int st) {
        int t = c >> 4, k0 = (c & 15) << 6;
        const __half* Ap = (t < 2) ? Ahi : Alo;
        const __half* Bp = (t == 1) ? Blo : Bhi;
#pragma unroll
        for (int it = 0; it < 4; ++it) {
            int idx = it * 256 + tid;
            int r = idx >> 3, k8 = (idx & 7) << 3;
            CP_A16(sbA + st * G_STAGE + swz_h(r, k8),
                   Ap + (size_t)(row0 + r) * 1024 + k0 + k8);
            CP_A16(sbB + st * G_STAGE + swz_h(r, k8),
                   Bp + (size_t)(col0 + r) * 1024 + k0 + k8);
        }
        CP_COMMIT();
    };

    issue(0, 0);
    for (int c = 0; c < nch; ++c) {
        if (c + 1 < nch) { issue(c + 1, (c + 1) & 1); CP_WAIT1(); }
        else             { CP_WAIT0(); }
        __syncthreads();
        const uint32_t aoff = sbA + (c & 1) * G_STAGE;
        const uint32_t boff = sbB + (c & 1) * G_STAGE;
#pragma unroll
        for (int kk = 0; kk < 64; kk += 16) {
            uint32_t af[2][4], bf[4][4];
#pragma unroll
            for (int mi = 0; mi < 2; ++mi)
                ldsm_x4(af[mi], aoff + swz_h(m0 + mi * 16 + lrow, kk + lkof));
#pragma unroll
            for (int g = 0; g < 4; ++g)
                ldsm_x4(bf[g], boff + swz_h(n0 + g * 16 + lrow, kk + lkof));
#pragma unroll
            for (int mi = 0; mi < 2; ++mi)
#pragma unroll
                for (int g = 0; g < 4; ++g) {
                    mma16816(acc[mi][2 * g],     af[mi], bf[g][0], bf[g][2]);
                    mma16816(acc[mi][2 * g + 1], af[mi], bf[g][1], bf[g][3]);
                }
        }
        __syncthreads();
    }

    // epilogue
    const int frow = m0 + (lane >> 2);
    const int fcol = n0 + 2 * (lane & 3);
#pragma unroll
    for (int mi = 0; mi < 2; ++mi) {
#pragma unroll
        for (int nj = 0; nj < 8; ++nj) {
            int col = col0 + fcol + nj * 8;
            int r0 = row0 + frow + mi * 16;
            float b0 = bias[col], b1 = bias[col + 1];
            float v0 = acc[mi][nj][0] + b0, v1 = acc[mi][nj][1] + b1;
            float v2 = acc[mi][nj][2] + b0, v3 = acc[mi][nj][3] + b1;
            if (mode == 0) {
                // extra LOG2E folded in so softmax can use raw ex2
                float p0 = pds[col & 63], p1 = pds[(col + 1) & 63];
                float s0 = (LOG2E_ * LOG2E_ * 0.125f) * ((p0 > 20.f) ? p0 : log1pf(__expf(p0)));
                float s1 = (LOG2E_ * LOG2E_ * 0.125f) * ((p1 > 20.f) ? p1 : log1pf(__expf(p1)));
                v0 *= s0; v1 *= s1; v2 *= s0; v3 *= s1;
            }
            if (mode <= 1) {
                __half* Chi = (mode == 0) ? g_qhi : g_khi;
                __half* Clo = (mode == 0) ? g_qlo : g_klo;
                uint32_t h, l;
                split2(v0, v1, h, l);
                *(uint32_t*)&Chi[(size_t)r0 * 1024 + col] = h;
                *(uint32_t*)&Clo[(size_t)r0 * 1024 + col] = l;
                split2(v2, v3, h, l);
                *(uint32_t*)&Chi[(size_t)(r0 + 8) * 1024 + col] = h;
                *(uint32_t*)&Clo[(size_t)(r0 + 8) * 1024 + col] = l;
            } else if (mode == 2) {
                *(uint32_t*)&g_v16[(size_t)r0 * 1024 + col] =
                    pack_h2(__float2half_rn(v0), __float2half_rn(v1));
                *(uint32_t*)&g_v16[(size_t)(r0 + 8) * 1024 + col] =
                    pack_h2(__float2half_rn(v2), __float2half_rn(v3));
            } else {
                *(float2*)&out[(size_t)r0 * 1024 + col] = make_float2(v0, v1);
                *(float2*)&out[(size_t)(r0 + 8) * 1024 + col] = make_float2(v2, v3);
            }
        }
    }
}

// ---------------------------------------------------------------------------
// Flash attention, HMMA. Block = (64 q rows, head n, batch b), 128 thr / 4 warps.
// QK^T 3-term with Kh-fragment reuse (load Kh once -> Qh*Kh + Ql*Kh; then
// load Kl -> Qh*Kl). PV single-term fp16 P (error linear downstream).
// ex2 softmax, byte mask. Output: fp16 hi only (out-proj 2-term never reads lo).
// smem: Qh,Ql [64][64] (16KB) + 2 stages of (Kh,Kl,V [64][64]) (48KB).
// ---------------------------------------------------------------------------
#define A_QOFF 0
#define A_KVOFF 16384
#define A_KVSTAGE 24576
#define ATTN_SMEM (16384 + 2 * 24576)
__global__ __launch_bounds__(128) void attn_hmma_kernel()
{
    extern __shared__ char smem[];
    const int tid = threadIdx.x;
    const int wid = tid >> 5, lane = tid & 31;
    const int q0 = blockIdx.x * 64;
    const int n  = blockIdx.y;
    const int b  = blockIdx.z;
    const uint32_t sb = smem_u32(smem);
    const int lrow = lane & 15;
    const int lkof = (lane & 16) >> 1;

    const size_t gq0 = (size_t)(b * TT + q0) * 1024 + n * 64;

#pragma unroll
    for (int it = 0; it < 4; ++it) {
        int idx = it * 128 + tid;
        int r = idx >> 3, k8 = (idx & 7) << 3;
        size_t g = gq0 + (size_t)r * 1024 + k8;
        uint32_t o = swz_h(r, k8);
        CP_A16(sb + A_QOFF + o,        g_qhi + g);
        CP_A16(sb + A_QOFF + 8192 + o, g_qlo + g);
    }
    auto issue_kv = [&](int st, int stage) {
        size_t gk0 = (size_t)(b * TT + st * 64) * 1024 + n * 64;
        uint32_t base = sb + A_KVOFF + stage * A_KVSTAGE;
#pragma unroll
        for (int it = 0; it < 4; ++it) {
            int idx = it * 128 + tid;
            int r = idx >> 3, k8 = (idx & 7) << 3;
            size_t g = gk0 + (size_t)r * 1024 + k8;
            uint32_t o = swz_h(r, k8);
            CP_A16(base + o,         g_khi + g);
            CP_A16(base + 8192 + o,  g_klo + g);
            CP_A16(base + 16384 + o, g_v16 + g);
        }
        CP_COMMIT();
    };
    issue_kv(0, 0);

    uint32_t qh[4][4], ql[4][4];
    float oacc[8][4];
#pragma unroll
    for (int j = 0; j < 8; ++j)
#pragma unroll
        for (int c = 0; c < 4; ++c) oacc[j][c] = 0.f;
    float m_0 = -3.0e38f, m_1 = -3.0e38f, l_0 = 0.f, l_1 = 0.f;

    const int qrl = q0 + wid * 16 + (lane >> 2);
    const int mcol0 = 2 * (lane & 3);
    const unsigned char* mrow0 = g_mask8 + (size_t)(b * TT + qrl) * TT + mcol0;
    const unsigned char* mrow1 = mrow0 + 8 * TT;

    for (int st = 0; st < TT / 64; ++st) {
        if (st + 1 < TT / 64) { issue_kv(st + 1, (st + 1) & 1); CP_WAIT1(); }
        else                  { CP_WAIT0(); }
        __syncthreads();

        if (st == 0) {
#pragma unroll
            for (int kt = 0; kt < 4; ++kt) {
                uint32_t o = swz_h(wid * 16 + lrow, kt * 16 + lkof);
                ldsm_x4(qh[kt], sb + A_QOFF + o);
                ldsm_x4(ql[kt], sb + A_QOFF + 8192 + o);
            }
        }

        const uint32_t kvb = sb + A_KVOFF + (st & 1) * A_KVSTAGE;

        // ---- S = QK^T: Kh phase (Qh*Kh + Ql*Kh), then Kl phase (Qh*Kl) ----
        float sacc[8][4];
#pragma unroll
        for (int j = 0; j < 8; ++j)
#pragma unroll
            for (int c = 0; c < 4; ++c) sacc[j][c] = 0.f;
#pragma unroll
        for (int kq = 0; kq < 4; ++kq) {
            uint32_t bf[4][4];
#pragma unroll
            for (int g = 0; g < 4; ++g)
                ldsm_x4(bf[g], kvb + swz_h(g * 16 + lrow, kq * 16 + lkof));
#pragma unroll
            for (int g = 0; g < 4; ++g) {
                mma16816(sacc[2 * g],     qh[kq], bf[g][0], bf[g][2]);
                mma16816(sacc[2 * g + 1], qh[kq], bf[g][1], bf[g][3]);
                mma16816(sacc[2 * g],     ql[kq], bf[g][0], bf[g][2]);
                mma16816(sacc[2 * g + 1], ql[kq], bf[g][1], bf[g][3]);
            }
        }
#pragma unroll
        for (int kq = 0; kq < 4; ++kq) {
            uint32_t bf[4][4];
#pragma unroll
            for (int g = 0; g < 4; ++g)
                ldsm_x4(bf[g], kvb + 8192 + swz_h(g * 16 + lrow, kq * 16 + lkof));
#pragma unroll
            for (int g = 0; g < 4; ++g) {
                mma16816(sacc[2 * g],     qh[kq], bf[g][0], bf[g][2]);
                mma16816(sacc[2 * g + 1], qh[kq], bf[g][1], bf[g][3]);
            }
        }

        // ---- mask (byte) ----
#pragma unroll
        for (int j = 0; j < 8; ++j) {
            int col = st * 64 + j * 8;
            uchar2 mv0 = *(const uchar2*)(mrow0 + col);
            uchar2 mv1 = *(const uchar2*)(mrow1 + col);
            if (!mv0.x) sacc[j][0] = -1.0e9f;
            if (!mv0.y) sacc[j][1] = -1.0e9f;
            if (!mv1.x) sacc[j][2] = -1.0e9f;
            if (!mv1.y) sacc[j][3] = -1.0e9f;
        }

        // ---- online softmax (log2 domain) ----
        float mx0 = -3.0e38f, mx1 = -3.0e38f;
#pragma unroll
        for (int j = 0; j < 8; ++j) {
            mx0 = fmaxf(mx0, fmaxf(sacc[j][0], sacc[j][1]));
            mx1 = fmaxf(mx1, fmaxf(sacc[j][2], sacc[j][3]));
        }
        mx0 = fmaxf(mx0, __shfl_xor_sync(0xffffffffu, mx0, 1));
        mx0 = fmaxf(mx0, __shfl_xor_sync(0xffffffffu, mx0, 2));
        mx1 = fmaxf(mx1, __shfl_xor_sync(0xffffffffu, mx1, 1));
        mx1 = fmaxf(mx1, __shfl_xor_sync(0xffffffffu, mx1, 2));
        float mn0 = fmaxf(m_0, mx0), mn1 = fmaxf(m_1, mx1);
        float f0 = ex2(m_0 - mn0), f1 = ex2(m_1 - mn1);
        m_0 = mn0; m_1 = mn1;
        float rs0 = 0.f, rs1 = 0.f;
#pragma unroll
        for (int j = 0; j < 8; ++j) {
            sacc[j][0] = ex2(sacc[j][0] - mn0);
            sacc[j][1] = ex2(sacc[j][1] - mn0);
            sacc[j][2] = ex2(sacc[j][2] - mn1);
            sacc[j][3] = ex2(sacc[j][3] - mn1);
            rs0 += sacc[j][0] + sacc[j][1];
            rs1 += sacc[j][2] + sacc[j][3];
        }
        rs0 += __shfl_xor_sync(0xffffffffu, rs0, 1);
        rs0 += __shfl_xor_sync(0xffffffffu, rs0, 2);
        rs1 += __shfl_xor_sync(0xffffffffu, rs1, 1);
        rs1 += __shfl_xor_sync(0xffffffffu, rs1, 2);
        l_0 = l_0 * f0 + rs0;
        l_1 = l_1 * f1 + rs1;
#pragma unroll
        for (int j = 0; j < 8; ++j) {
            oacc[j][0] *= f0; oacc[j][1] *= f0;
            oacc[j][2] *= f1; oacc[j][3] *= f1;
        }

        // ---- O += P V (single-term fp16 P, fp16 V) ----
#pragma unroll
        for (int kt = 0; kt < 4; ++kt) {
            uint32_t ph[4];
            {
                const float* sA = sacc[2 * kt];
                const float* sB = sacc[2 * kt + 1];
                ph[0] = pack_h2(__float2half_rn(sA[0]), __float2half_rn(sA[1]));
                ph[1] = pack_h2(__float2half_rn(sA[2]), __float2half_rn(sA[3]));
                ph[2] = pack_h2(__float2half_rn(sB[0]), __float2half_rn(sB[1]));
                ph[3] = pack_h2(__float2half_rn(sB[2]), __float2half_rn(sB[3]));
            }
            uint32_t vf[4][4];
#pragma unroll
            for (int g = 0; g < 4; ++g)
                ldsm_x4_t(vf[g], kvb + 16384 + swz_h(kt * 16 + lrow, g * 16 + lkof));
#pragma unroll
            for (int g = 0; g < 4; ++g) {
                mma16816(oacc[2 * g],     ph, vf[g][0], vf[g][1]);
                mma16816(oacc[2 * g + 1], ph, vf[g][2], vf[g][3]);
            }
        }
        __syncthreads();
    }

    // ---- epilogue: normalize + fp16 store (hi only) ----
    const float inv0 = 1.0f / l_0, inv1 = 1.0f / l_1;
    const size_t m_lo = (size_t)(b * TT + qrl) * 1024 + n * 64;
#pragma unroll
    for (int j = 0; j < 8; ++j) {
        int col = j * 8 + mcol0;
        *(uint32_t*)&g_ahi[m_lo + col] =
            pack_h2(__float2half_rn(oacc[j][0] * inv0), __float2half_rn(oacc[j][1] * inv0));
        *(uint32_t*)&g_ahi[m_lo + 8 * 1024 + col] =
            pack_h2(__float2half_rn(oacc[j][2] * inv1), __float2half_rn(oacc[j][3] * inv1));
    }
}

// ---------------------------------------------------------------------------
// Launch
// ---------------------------------------------------------------------------
extern "C" void kernel_launch(void* const* d_in, const int* in_sizes, int n_in,
                              void* d_out, int out_size)
{
    const float* x    = (const float*)d_in[0];
    const int*   mask = (const int*)  d_in[1];
    const float* wq   = (const float*)d_in[2];
    const float* bq   = (const float*)d_in[3];
    const float* wk   = (const float*)d_in[4];
    const float* bk   = (const float*)d_in[5];
    const float* wv   = (const float*)d_in[6];
    const float* bv   = (const float*)d_in[7];
    const float* wo   = (const float*)d_in[8];
    const float* bo   = (const float*)d_in[9];
    const float* pds  = (const float*)d_in[10];
    float* out = (float*)d_out;

    const int gemm_smem = 4 * G_STAGE;  // 64KB
    cudaFuncSetAttribute(gemm_split_kernel, cudaFuncAttributeMaxDynamicSharedMemorySize, gemm_smem);
    cudaFuncSetAttribute(attn_hmma_kernel, cudaFuncAttributeMaxDynamicSharedMemorySize, ATTN_SMEM);

    __half *xhi, *xlo, *wohi, *wolo;
    cudaGetSymbolAddress((void**)&xhi, g_xhi);
    cudaGetSymbolAddress((void**)&xlo, g_xlo);
    cudaGetSymbolAddress((void**)&wohi, g_wohi);
    cudaGetSymbolAddress((void**)&wolo, g_wolo);

    split_kernel<<<4096, 256>>>(x, xhi, xlo, 1048576);
    split_kernel<<<1024, 256>>>(wo, wohi, wolo, 262144);
    mask_pack_kernel<<<8192, 256>>>(mask);
    transpose_split_kernel<<<dim3(32, 32, 3), dim3(32, 8)>>>(wq, wk, wv);

    gemm_split_kernel<<<dim3(8, 32, 3), 256, gemm_smem>>>(bq, bk, bv, bo, pds, out, 0);
    attn_hmma_kernel<<<dim3(32, 16, 2), 128, ATTN_SMEM>>>();
    gemm_split_kernel<<<dim3(8, 32, 1), 256, gemm_smem>>>(bq, bk, bv, bo, pds, out, 3);
}